// round 12
// baseline (speedup 1.0000x reference)
#include <cuda_runtime.h>
#include <cuda_fp16.h>
#include <math.h>
#include <stdint.h>

#define NN 100000
#define EE 1600000
#define FIN 512
#define HH 128
#define KKEEP 50000
#define NCH 98  // ceil(NN/1024)

typedef unsigned long long ull;

// ------------------------- device scratch (globals) -------------------------
__device__ __align__(16) uint32_t g_yh[(size_t)NN * 64];  // y = X@W as half2 pairs (unscaled)
__device__ __align__(16) float g_x1[(size_t)NN * HH];
__device__ __align__(16) float g_x2[(size_t)NN * HH];
__device__ __align__(16) float g_x3[(size_t)NN * HH];
__device__ int   g_degcnt[NN];
__device__ float g_dsf[NN];
__device__ int   g_rowptr[NN + 1];
__device__ int   g_fill[NN];
__device__ int   g_csr[EE];
__device__ int   g_chunksum[NCH];
__device__ int   g_chunkoff[NCH];
__device__ float g_ysc[NN];
__device__ float g_score[NN];
__device__ float g_gate[NN];
__device__ unsigned g_ukey[NN];
__device__ unsigned g_hist[256];
__device__ unsigned g_prefix;
__device__ unsigned g_kprime;
__device__ int   g_nties;
__device__ int   g_tieidx[NN];
__device__ int   g_tieflag[NN];
__device__ float g_gmax[384];
__device__ float g_gsum[384];
// pre-split B (W^T) fragments per layer, bf16 hi/lo, chunk-major: [layer][chunk][2048]
__device__ __align__(16) uint32_t g_bhi[3 * 16 * 2048];
__device__ __align__(16) uint32_t g_blo[3 * 16 * 2048];

// ------------------------- small helpers -------------------------
__device__ __forceinline__ unsigned fkey(float f) {
    unsigned u = __float_as_uint(f);
    return (u & 0x80000000u) ? ~u : (u | 0x80000000u);
}
__device__ __forceinline__ void atomicMaxF(float *addr, float val) {
    if (val >= 0.f) atomicMax((int *)addr, __float_as_int(val));
    else            atomicMin((unsigned *)addr, __float_as_uint(val));
}
__device__ __forceinline__ const float *pickX(int w) {
    return w == 1 ? g_x1 : (w == 2 ? g_x2 : g_x3);
}
__device__ __forceinline__ uint32_t pack_bf16x2(float x, float y) {
    uint32_t r;
    asm("cvt.rn.bf16x2.f32 %0, %1, %2;" : "=r"(r) : "f"(y), "f"(x));
    return r;
}
__device__ __forceinline__ float bf16lo_f(uint32_t p) { return __uint_as_float(p << 16); }
__device__ __forceinline__ float bf16hi_f(uint32_t p) { return __uint_as_float(p & 0xFFFF0000u); }
__device__ __forceinline__ void split2_bf16(float x, float y, uint32_t &hi, uint32_t &lo) {
    hi = pack_bf16x2(x, y);
    lo = pack_bf16x2(x - bf16lo_f(hi), y - bf16hi_f(hi));
}
__device__ __forceinline__ void mma16816(float *d, const uint32_t *a, const uint32_t *b) {
    asm volatile("mma.sync.aligned.m16n8k16.row.col.f32.bf16.bf16.f32 "
                 "{%0,%1,%2,%3}, {%4,%5,%6,%7}, {%8,%9}, {%0,%1,%2,%3};"
                 : "+f"(d[0]), "+f"(d[1]), "+f"(d[2]), "+f"(d[3])
                 : "r"(a[0]), "r"(a[1]), "r"(a[2]), "r"(a[3]), "r"(b[0]), "r"(b[1]));
}
#define CP_ASYNC8(dst_u32, src_ptr, szreg) \
    asm volatile("cp.async.ca.shared.global [%0], [%1], 8, %2;" \
                 :: "r"(dst_u32), "l"(src_ptr), "r"(szreg))
#define CP_ASYNC16(dst_u32, src_ptr) \
    asm volatile("cp.async.cg.shared.global [%0], [%1], 16;" \
                 :: "r"(dst_u32), "l"(src_ptr))
#define CP_COMMIT() asm volatile("cp.async.commit_group;" ::: "memory")
#define CP_WAIT1() asm volatile("cp.async.wait_group 1;" ::: "memory")
#define CP_WAIT0() asm volatile("cp.async.wait_group 0;" ::: "memory")

// ------------------------- init -------------------------
__global__ void k_init() {
    int i = blockIdx.x * blockDim.x + threadIdx.x;
    if (i < NN) { g_degcnt[i] = 0; g_fill[i] = 0; g_tieflag[i] = 0; }
    if (i < 384) { g_gmax[i] = -3.402823466e38f; g_gsum[i] = 0.f; }
    if (i < 256) g_hist[i] = 0u;
    if (i == 0) { g_prefix = 0u; g_kprime = (unsigned)KKEEP; g_nties = 0; }
}

// ------------------------- B prep: split W[Kin,128] into fragment-major bf16 hi/lo ----
__global__ void k_prepB(const float *__restrict__ W, int Kin, int layer) {
    int i = blockIdx.x * blockDim.x + threadIdx.x;   // pair index
    if (i >= Kin * 64) return;
    int kp = i >> 7, n = i & 127;
    int k = kp * 2;
    float w0 = W[(size_t)k * 128 + n];
    float w1 = W[(size_t)(k + 1) * 128 + n];
    int c = k >> 5;
    int kk = k & 31;
    int nt = n >> 3, ks = kk >> 4;
    int r = ((kk & 15) >= 8) ? 1 : 0;
    int lane_b = (n & 7) * 4 + ((kk & 7) >> 1);
    int base = layer * 32768 + c * 2048 + ((nt * 2 + ks) * 32 + lane_b) * 2 + r;
    uint32_t h, l;
    split2_bf16(w0, w1, h, l);
    g_bhi[base] = h;
    g_blo[base] = l;
}

// ------------------------- degree / CSR build (edge_index is int32) -------------------------
__global__ void k_count(const int *__restrict__ ei) {
    int e4 = blockIdx.x * blockDim.x + threadIdx.x;
    if (e4 >= EE / 4) return;
    int4 d = *(const int4 *)&ei[EE + e4 * 4];
    atomicAdd(&g_degcnt[d.x], 1);
    atomicAdd(&g_degcnt[d.y], 1);
    atomicAdd(&g_degcnt[d.z], 1);
    atomicAdd(&g_degcnt[d.w], 1);
}
__global__ void k_dsf() {
    int i = blockIdx.x * blockDim.x + threadIdx.x;
    if (i < NN) g_dsf[i] = rsqrtf((float)(g_degcnt[i] + 1));
}
__global__ void k_chunksum() {
    __shared__ int sm[256];
    int t = threadIdx.x, b = blockIdx.x;
    int s = 0;
    for (int j = t; j < 1024; j += 256) {
        int idx = b * 1024 + j;
        if (idx < NN) s += g_degcnt[idx];
    }
    sm[t] = s; __syncthreads();
    for (int o = 128; o; o >>= 1) { if (t < o) sm[t] += sm[t + o]; __syncthreads(); }
    if (t == 0) g_chunksum[b] = sm[0];
}
__global__ void k_scanchunks() {
    int run = 0;
    for (int c = 0; c < NCH; ++c) { g_chunkoff[c] = run; run += g_chunksum[c]; }
    g_rowptr[NN] = EE;
}
__global__ void k_scanwrite() {
    __shared__ int sd[1024];
    int t = threadIdx.x, b = blockIdx.x;
    int idx = b * 1024 + t;
    int v = (idx < NN) ? g_degcnt[idx] : 0;
    int x = v;
    for (int o = 1; o < 1024; o <<= 1) {
        sd[t] = x; __syncthreads();
        if (t >= o) x += sd[t - o];
        __syncthreads();
    }
    if (idx < NN) g_rowptr[idx] = g_chunkoff[b] + x - v;
}
__global__ void k_scatter(const int *__restrict__ ei) {
    int e4 = blockIdx.x * blockDim.x + threadIdx.x;
    if (e4 >= EE / 4) return;
    int4 s = *(const int4 *)&ei[e4 * 4];
    int4 d = *(const int4 *)&ei[EE + e4 * 4];
    g_csr[g_rowptr[d.x] + atomicAdd(&g_fill[d.x], 1)] = s.x;
    g_csr[g_rowptr[d.y] + atomicAdd(&g_fill[d.y], 1)] = s.y;
    g_csr[g_rowptr[d.z] + atomicAdd(&g_fill[d.z], 1)] = s.z;
    g_csr[g_rowptr[d.w] + atomicAdd(&g_fill[d.w], 1)] = s.w;
}

// ------------------------- GEMM: cp.async pipeline carrying A (f32) + B hi/lo (bf16) ----
// y = X@W (unscaled) stored as half2 pairs into g_yh.
#define GPIPE 3
#define GSTAGE 32768
#define GT_SMEM_BYTES (GPIPE * GSTAGE)
__global__ __launch_bounds__(256, 2) void k_gemm_mma(const float *__restrict__ Aext, int useExt,
                                                     int whichSrc, int Kin, int layer) {
    extern __shared__ char smem[];
    const float *A = useExt ? Aext : pickX(whichSrc);
    uint32_t sbase = (uint32_t)__cvta_generic_to_shared(smem);
    const uint32_t *bhi = g_bhi + layer * 32768;
    const uint32_t *blo = g_blo + layer * 32768;

    int tid = threadIdx.x, wid = tid >> 5, lane = tid & 31;
    int wm = wid & 3, wn = wid >> 2;
    int row0 = blockIdx.x * 128;

    int cp_m[8], cp_dst[8];
    const float *cp_src[8];
#pragma unroll
    for (int it = 0; it < 8; ++it) {
        int i = tid + it * 256;
        int m = i >> 4, p = i & 15;
        int mt = m >> 4, ks = p >> 3;
        int l = (m & 7) * 4 + (p & 3);
        int off = 2 * (((m & 15) >= 8) ? 1 : 0) + 4 * (((p & 7) >= 4) ? 1 : 0);
        int fidx = ((mt * 2 + ks) * 32 + l) * 8 + off;
        cp_m[it] = m;
        cp_dst[it] = fidx * 4;
        cp_src[it] = A + (size_t)(row0 + m) * Kin + p * 2;
    }

    float acc[2][8][4];
#pragma unroll
    for (int mt = 0; mt < 2; ++mt)
#pragma unroll
        for (int nt = 0; nt < 8; ++nt)
#pragma unroll
            for (int q = 0; q < 4; ++q) acc[mt][nt][q] = 0.f;

    int nchunks = Kin >> 5;

    auto issue = [&](int c, int buf) {
        uint32_t bb = sbase + buf * GSTAGE;
#pragma unroll
        for (int it = 0; it < 8; ++it) {
            int valid = (row0 + cp_m[it] < NN) ? 8 : 0;
            CP_ASYNC8(bb + cp_dst[it], cp_src[it] + c * 32, valid);
        }
#pragma unroll
        for (int j = 0; j < 2; ++j) {
            int idx = tid + j * 256;
            CP_ASYNC16(bb + 16384 + idx * 16, (const char *)&bhi[c * 2048 + idx * 4]);
            CP_ASYNC16(bb + 24576 + idx * 16, (const char *)&blo[c * 2048 + idx * 4]);
        }
    };

    issue(0, 0); CP_COMMIT();
    issue(1, 1); CP_COMMIT();

    for (int c = 0; c < nchunks; ++c) {
        if (c + 1 < nchunks) { CP_WAIT1(); } else { CP_WAIT0(); }
        __syncthreads();
        if (c + 2 < nchunks) { issue(c + 2, (c + 2) % GPIPE); CP_COMMIT(); }

        const char *stg = smem + (c % GPIPE) * GSTAGE;
        const float *fa = (const float *)stg;
        const uint32_t *fbh = (const uint32_t *)(stg + 16384);
        const uint32_t *fbl = (const uint32_t *)(stg + 24576);
#pragma unroll
        for (int ks = 0; ks < 2; ++ks) {
            uint32_t ah[2][4], al[2][4];
#pragma unroll
            for (int mt = 0; mt < 2; ++mt) {
                int mtg = wm * 2 + mt;
                const float4 *p4 = (const float4 *)&fa[((mtg * 2 + ks) * 32 + lane) * 8];
                float4 u = p4[0], v = p4[1];
                split2_bf16(u.x, u.y, ah[mt][0], al[mt][0]);
                split2_bf16(u.z, u.w, ah[mt][1], al[mt][1]);
                split2_bf16(v.x, v.y, ah[mt][2], al[mt][2]);
                split2_bf16(v.z, v.w, ah[mt][3], al[mt][3]);
            }
#pragma unroll
            for (int nt = 0; nt < 8; ++nt) {
                int ntg = wn * 8 + nt;
                int bidx = ((ntg * 2 + ks) * 32 + lane) * 2;
                uint2 vh = *(const uint2 *)&fbh[bidx];
                uint2 vl = *(const uint2 *)&fbl[bidx];
                uint32_t bh[2] = {vh.x, vh.y};
                uint32_t bl[2] = {vl.x, vl.y};
#pragma unroll
                for (int mt = 0; mt < 2; ++mt) {
                    mma16816(acc[mt][nt], ah[mt], bh);
                    mma16816(acc[mt][nt], ah[mt], bl);
                    mma16816(acc[mt][nt], al[mt], bh);
                }
            }
        }
    }

    // ---- epilogue: y (unscaled) stored as half2 into g_yh ----
    int r = lane >> 2;
#pragma unroll
    for (int mt = 0; mt < 2; ++mt) {
        int rbase = row0 + wm * 32 + mt * 16 + r;
#pragma unroll
        for (int half = 0; half < 2; ++half) {
            int row = rbase + half * 8;
            if (row >= NN) continue;
            uint32_t *dst = &g_yh[(size_t)row * 64 + wn * 32 + (lane & 3)];
#pragma unroll
            for (int nt = 0; nt < 8; ++nt) {
                half2 h = __floats2half2_rn(acc[mt][nt][half * 2 + 0],
                                            acc[mt][nt][half * 2 + 1]);
                dst[nt * 4] = *(uint32_t *)&h;
            }
        }
    }
}

// ------------------------- aggregation: out = relu(ds[d]*(sum_nb ds[s]*y[s] + ds[d]*y[d]) + b) ----
__global__ __launch_bounds__(256) void k_agg(const float *__restrict__ bias, int whichDst,
                                             int fuseScore, const float *__restrict__ Ws) {
    int gw = (blockIdx.x * 256 + threadIdx.x) >> 5;
    int lane = threadIdx.x & 31;
    if (gw >= NN) return;
    float *out = (float *)pickX(whichDst);
    int start = g_rowptr[gw], end = g_rowptr[gw + 1];
    int cu = lane * 2;
    float sc = g_dsf[gw];
    uint2 sv = *(const uint2 *)&g_yh[(size_t)gw * 64 + cu];
    float2 s0 = __half22float2(*(half2 *)&sv.x);
    float2 s1 = __half22float2(*(half2 *)&sv.y);
    float4 acc = make_float4(s0.x * sc, s0.y * sc, s1.x * sc, s1.y * sc);  // self
    int e = start;
    for (; e + 4 <= end; e += 4) {
        int n0 = g_csr[e], n1 = g_csr[e + 1], n2 = g_csr[e + 2], n3 = g_csr[e + 3];
        float w0 = g_dsf[n0], w1 = g_dsf[n1], w2 = g_dsf[n2], w3 = g_dsf[n3];
        uint2 v0 = *(const uint2 *)&g_yh[(size_t)n0 * 64 + cu];
        uint2 v1 = *(const uint2 *)&g_yh[(size_t)n1 * 64 + cu];
        uint2 v2 = *(const uint2 *)&g_yh[(size_t)n2 * 64 + cu];
        uint2 v3 = *(const uint2 *)&g_yh[(size_t)n3 * 64 + cu];
        float2 a0 = __half22float2(*(half2 *)&v0.x), b0 = __half22float2(*(half2 *)&v0.y);
        float2 a1 = __half22float2(*(half2 *)&v1.x), b1 = __half22float2(*(half2 *)&v1.y);
        float2 a2 = __half22float2(*(half2 *)&v2.x), b2 = __half22float2(*(half2 *)&v2.y);
        float2 a3 = __half22float2(*(half2 *)&v3.x), b3 = __half22float2(*(half2 *)&v3.y);
        acc.x += w0 * a0.x + w1 * a1.x + w2 * a2.x + w3 * a3.x;
        acc.y += w0 * a0.y + w1 * a1.y + w2 * a2.y + w3 * a3.y;
        acc.z += w0 * b0.x + w1 * b1.x + w2 * b2.x + w3 * b3.x;
        acc.w += w0 * b0.y + w1 * b1.y + w2 * b2.y + w3 * b3.y;
    }
    for (; e < end; ++e) {
        int n = g_csr[e];
        float w = g_dsf[n];
        uint2 v = *(const uint2 *)&g_yh[(size_t)n * 64 + cu];
        float2 a = __half22float2(*(half2 *)&v.x), b = __half22float2(*(half2 *)&v.y);
        acc.x += w * a.x; acc.y += w * a.y; acc.z += w * b.x; acc.w += w * b.y;
    }
    int c0 = lane * 4;
    float4 b4 = *(const float4 *)&bias[c0];
    float4 o;
    o.x = fmaxf(fmaf(acc.x, sc, b4.x), 0.f);
    o.y = fmaxf(fmaf(acc.y, sc, b4.y), 0.f);
    o.z = fmaxf(fmaf(acc.z, sc, b4.z), 0.f);
    o.w = fmaxf(fmaf(acc.w, sc, b4.w), 0.f);
    *(float4 *)&out[(size_t)gw * 128 + c0] = o;

    if (fuseScore) {
        float4 w1 = *(const float4 *)&Ws[c0];
        float4 w2 = *(const float4 *)&Ws[128 + c0];
        float4 w3 = *(const float4 *)&Ws[256 + c0];
        float4 x1v = *(const float4 *)&g_x1[(size_t)gw * 128 + c0];
        float4 x2v = *(const float4 *)&g_x2[(size_t)gw * 128 + c0];
        float s = x1v.x * w1.x + x1v.y * w1.y + x1v.z * w1.z + x1v.w * w1.w
                + x2v.x * w2.x + x2v.y * w2.y + x2v.z * w2.z + x2v.w * w2.w
                + o.x * w3.x + o.y * w3.y + o.z * w3.z + o.w * w3.w;
        for (int off = 16; off; off >>= 1) s += __shfl_down_sync(0xFFFFFFFFu, s, off);
        if (lane == 0) g_ysc[gw] = sc * s;
    }
}

// ------------------------- score aggregate (scalar GCN) + radix pass-0 hist -----------
__global__ __launch_bounds__(256) void k_score_agg(const float *__restrict__ bs) {
    int gw = (blockIdx.x * 256 + threadIdx.x) >> 5;
    int lane = threadIdx.x & 31;
    if (gw >= NN) return;
    int start = g_rowptr[gw], end = g_rowptr[gw + 1];
    float s = 0.f;
    for (int e = start + lane; e < end; e += 32) s += g_ysc[g_csr[e]];
    for (int o = 16; o; o >>= 1) s += __shfl_down_sync(0xFFFFFFFFu, s, o);
    if (lane == 0) {
        float tot = s + g_ysc[gw];
        float sc = fmaf(g_dsf[gw], tot, bs[0]);
        g_score[gw] = sc;
        unsigned k = fkey(sc);
        g_ukey[gw] = k;
        atomicAdd(&g_hist[k >> 24], 1u);   // fused radix pass-0 histogram
    }
}

// ------------------------- radix select (passes 1..3 of 8 bits) -------------------------
__global__ void k_hist(int pass) {
    __shared__ unsigned sh[256];
    int t = threadIdx.x;
    sh[t] = 0u; __syncthreads();
    int i = blockIdx.x * 256 + t;
    if (i < NN) {
        unsigned u = g_ukey[i];
        bool m = ((u >> (32 - 8 * pass)) == g_prefix);
        if (m) atomicAdd(&sh[(u >> (24 - 8 * pass)) & 255u], 1u);
    }
    __syncthreads();
    if (sh[t]) atomicAdd(&g_hist[t], sh[t]);
}
__global__ void k_select() {
    __shared__ unsigned h[256];
    int t = threadIdx.x;
    h[t] = g_hist[t];
    g_hist[t] = 0u;
    __syncthreads();
    if (t == 0) {
        unsigned kp = g_kprime, c = 0;
        int b;
        for (b = 255; b >= 0; --b) {
            if (c + h[b] >= kp) break;
            c += h[b];
        }
        if (b < 0) b = 0;
        g_prefix = (g_prefix << 8) | (unsigned)b;
        g_kprime = kp - c;
    }
}
__global__ void k_ties() {
    int i = blockIdx.x * blockDim.x + threadIdx.x;
    if (i >= NN) return;
    g_gate[i] = tanhf(g_score[i]);       // precompute pool gate (1 pass)
    if (g_ukey[i] == g_prefix) {
        int p = atomicAdd(&g_nties, 1);
        g_tieidx[p] = i;
    }
}
__global__ void k_tieresolve() {
    int M = g_nties;
    unsigned R = g_kprime;
    for (int j = threadIdx.x; j < M; j += blockDim.x) {
        int idx = g_tieidx[j];
        unsigned rank = 0;
        for (int l = 0; l < M; ++l) rank += (g_tieidx[l] < idx) ? 1u : 0u;
        if (rank < R) g_tieflag[idx] = 1;
    }
}

// ------------------------- pooling (max + sum over kept nodes, 384 dims) -------------------------
__global__ __launch_bounds__(384) void k_pool() {
    int c = threadIdx.x;
    const float *xa = (c < 128) ? g_x1 : ((c < 256) ? g_x2 : g_x3);
    int cc = c & 127;
    unsigned T = g_prefix;
    float mx = -3.402823466e38f, sm = 0.f;
    for (int i = blockIdx.x; i < NN; i += gridDim.x) {
        unsigned u = g_ukey[i];
        if (u < T) continue;
        if (u == T && !g_tieflag[i]) continue;
        float g = g_gate[i];
        float v = xa[(size_t)i * 128 + cc] * g;
        mx = fmaxf(mx, v);
        sm += v;
    }
    atomicMaxF(&g_gmax[c], mx);
    atomicAdd(&g_gsum[c], sm);
}

// ------------------------- final MLP head (single block) -------------------------
__global__ __launch_bounds__(128) void k_mlp(const float *__restrict__ Wl1, const float *__restrict__ bl1,
                                             const float *__restrict__ Wl2, const float *__restrict__ bl2,
                                             const float *__restrict__ Wl3, const float *__restrict__ bl3,
                                             float *__restrict__ out) {
    __shared__ float h[768], h1[128], h2[64], lg[10];
    int t = threadIdx.x;
    for (int c = t; c < 384; c += 128) {
        h[c] = g_gmax[c];
        h[384 + c] = g_gsum[c] * (1.0f / KKEEP);
    }
    __syncthreads();
    float s = bl1[t];
    for (int i = 0; i < 768; ++i) s = fmaf(h[i], Wl1[i * 128 + t], s);
    h1[t] = fmaxf(s, 0.f);
    __syncthreads();
    if (t < 64) {
        float s2 = bl2[t];
        for (int i = 0; i < 128; ++i) s2 = fmaf(h1[i], Wl2[i * 64 + t], s2);
        h2[t] = fmaxf(s2, 0.f);
    }
    __syncthreads();
    if (t < 10) {
        float s3 = bl3[t];
        for (int i = 0; i < 64; ++i) s3 = fmaf(h2[i], Wl3[i * 10 + t], s3);
        lg[t] = s3;
    }
    __syncthreads();
    if (t == 0) {
        float m = lg[0];
        for (int j = 1; j < 10; ++j) m = fmaxf(m, lg[j]);
        float se = 0.f;
        for (int j = 0; j < 10; ++j) se += expf(lg[j] - m);
        float lse = m + logf(se);
        for (int j = 0; j < 10; ++j) out[j] = lg[j] - lse;
    }
}

// ------------------------- launch -------------------------
extern "C" void kernel_launch(void *const *d_in, const int *in_sizes, int n_in,
                              void *d_out, int out_size) {
    const float *x      = (const float *)d_in[0];
    const int   *ei     = (const int *)d_in[1];   // int32
    const float *W1 = (const float *)d_in[3],  *b1  = (const float *)d_in[4];
    const float *W2 = (const float *)d_in[5],  *b2  = (const float *)d_in[6];
    const float *W3 = (const float *)d_in[7],  *b3  = (const float *)d_in[8];
    const float *Ws = (const float *)d_in[9],  *bs  = (const float *)d_in[10];
    const float *Wl1 = (const float *)d_in[11], *bl1 = (const float *)d_in[12];
    const float *Wl2 = (const float *)d_in[13], *bl2 = (const float *)d_in[14];
    const float *Wl3 = (const float *)d_in[15], *bl3 = (const float *)d_in[16];
    float *out = (float *)d_out;

    const int nblkN = (NN + 255) / 256;
    const int nblkE4 = (EE / 4 + 255) / 256;
    const int nblkW = (NN * 32 + 255) / 256;
    const int nblkT = (NN + 127) / 128;

    static cudaStream_t sCsr = nullptr, sPrep = nullptr;
    static cudaEvent_t evFork = nullptr, evCsr = nullptr, evPrep = nullptr;
    static bool inited = false;
    if (!inited) {
        cudaStreamCreateWithFlags(&sCsr, cudaStreamNonBlocking);
        cudaStreamCreateWithFlags(&sPrep, cudaStreamNonBlocking);
        cudaEventCreateWithFlags(&evFork, cudaEventDisableTiming);
        cudaEventCreateWithFlags(&evCsr, cudaEventDisableTiming);
        cudaEventCreateWithFlags(&evPrep, cudaEventDisableTiming);
        cudaFuncSetAttribute(k_gemm_mma, cudaFuncAttributeMaxDynamicSharedMemorySize, GT_SMEM_BYTES);
        inited = true;
    }

    // ---- origin: init + prepB1 (GEMM-1 deps only) ----
    k_init<<<nblkN, 256>>>();
    cudaEventRecord(evFork, 0);
    k_prepB<<<(FIN * 64 + 255) / 256, 256>>>(W1, FIN, 0);

    // ---- side stream 1: edge pipeline (count -> dsf -> CSR), overlaps GEMM-1 ----
    cudaStreamWaitEvent(sCsr, evFork, 0);
    k_count<<<nblkE4, 256, 0, sCsr>>>(ei);
    k_dsf<<<nblkN, 256, 0, sCsr>>>();
    k_chunksum<<<NCH, 256, 0, sCsr>>>();
    k_scanchunks<<<1, 1, 0, sCsr>>>();
    k_scanwrite<<<NCH, 1024, 0, sCsr>>>();
    k_scatter<<<nblkE4, 256, 0, sCsr>>>(ei);
    cudaEventRecord(evCsr, sCsr);

    // ---- side stream 2: prepB layers 1,2 ----
    cudaStreamWaitEvent(sPrep, evFork, 0);
    k_prepB<<<(HH * 64 + 255) / 256, 256, 0, sPrep>>>(W2, HH, 1);
    k_prepB<<<(HH * 64 + 255) / 256, 256, 0, sPrep>>>(W3, HH, 2);
    cudaEventRecord(evPrep, sPrep);

    // ---- origin: GCN layer 1 GEMM (concurrent with edge pipeline) ----
    k_gemm_mma<<<nblkT, 256, GT_SMEM_BYTES>>>(x, 1, 0, FIN, 0);
    cudaStreamWaitEvent(0, evCsr, 0);
    k_agg<<<nblkW, 256>>>(b1, 1, 0, nullptr);
    // layer 2
    cudaStreamWaitEvent(0, evPrep, 0);
    k_gemm_mma<<<nblkT, 256, GT_SMEM_BYTES>>>(nullptr, 0, 1, HH, 1);
    k_agg<<<nblkW, 256>>>(b2, 2, 0, nullptr);
    // layer 3 (+fused score linear)
    k_gemm_mma<<<nblkT, 256, GT_SMEM_BYTES>>>(nullptr, 0, 2, HH, 2);
    k_agg<<<nblkW, 256>>>(b3, 3, 1, Ws);
    // score aggregate (+fused radix pass-0 hist)
    k_score_agg<<<nblkW, 256>>>(bs);
    k_select<<<1, 256>>>();
    for (int p = 1; p < 4; ++p) {
        k_hist<<<nblkN, 256>>>(p);
        k_select<<<1, 256>>>();
    }
    k_ties<<<nblkN, 256>>>();
    k_tieresolve<<<1, 256>>>();
    // gated max/mean readout over kept nodes
    k_pool<<<512, 384>>>();
    // MLP head + log_softmax
    k_mlp<<<1, 128>>>(Wl1, bl1, Wl2, bl2, Wl3, bl3, out);
}

// round 13
// speedup vs baseline: 1.0272x; 1.0272x over previous
#include <cuda_runtime.h>
#include <cuda_fp16.h>
#include <math.h>
#include <stdint.h>

#define NN 100000
#define EE 1600000
#define FIN 512
#define HH 128
#define KKEEP 50000
#define NCH 98  // ceil(NN/1024)

typedef unsigned long long ull;

// ------------------------- device scratch (globals) -------------------------
__device__ __align__(16) uint32_t g_yh[(size_t)NN * 64];  // y = ds*(X@W) as half2 pairs
__device__ __align__(16) float g_x1[(size_t)NN * HH];
__device__ __align__(16) float g_x2[(size_t)NN * HH];
__device__ __align__(16) float g_x3[(size_t)NN * HH];
__device__ int   g_degcnt[NN];
__device__ int   g_rowptr[NN + 1];
__device__ int   g_fill[NN];
__device__ int   g_csr[EE];
__device__ int   g_chunksum[NCH];
__device__ int   g_chunkoff[NCH];
__device__ float g_ysc[NN];
__device__ float g_score[NN];
__device__ float g_gate[NN];
__device__ unsigned g_ukey[NN];
__device__ unsigned g_hist[256];
__device__ unsigned g_prefix;
__device__ unsigned g_kprime;
__device__ int   g_nties;
__device__ int   g_tieidx[NN];
__device__ int   g_tieflag[NN];
__device__ float g_gmax[384];
__device__ float g_gsum[384];
// pre-split B (W^T) fragments per layer, bf16 hi/lo, chunk-major: [layer][chunk][2048]
__device__ __align__(16) uint32_t g_bhi[3 * 16 * 2048];
__device__ __align__(16) uint32_t g_blo[3 * 16 * 2048];

// ------------------------- small helpers -------------------------
__device__ __forceinline__ unsigned fkey(float f) {
    unsigned u = __float_as_uint(f);
    return (u & 0x80000000u) ? ~u : (u | 0x80000000u);
}
__device__ __forceinline__ void atomicMaxF(float *addr, float val) {
    if (val >= 0.f) atomicMax((int *)addr, __float_as_int(val));
    else            atomicMin((unsigned *)addr, __float_as_uint(val));
}
__device__ __forceinline__ const float *pickX(int w) {
    return w == 1 ? g_x1 : (w == 2 ? g_x2 : g_x3);
}
__device__ __forceinline__ uint32_t pack_bf16x2(float x, float y) {
    uint32_t r;
    asm("cvt.rn.bf16x2.f32 %0, %1, %2;" : "=r"(r) : "f"(y), "f"(x));
    return r;
}
__device__ __forceinline__ float bf16lo_f(uint32_t p) { return __uint_as_float(p << 16); }
__device__ __forceinline__ float bf16hi_f(uint32_t p) { return __uint_as_float(p & 0xFFFF0000u); }
__device__ __forceinline__ void split2_bf16(float x, float y, uint32_t &hi, uint32_t &lo) {
    hi = pack_bf16x2(x, y);
    lo = pack_bf16x2(x - bf16lo_f(hi), y - bf16hi_f(hi));
}
__device__ __forceinline__ void mma16816(float *d, const uint32_t *a, const uint32_t *b) {
    asm volatile("mma.sync.aligned.m16n8k16.row.col.f32.bf16.bf16.f32 "
                 "{%0,%1,%2,%3}, {%4,%5,%6,%7}, {%8,%9}, {%0,%1,%2,%3};"
                 : "+f"(d[0]), "+f"(d[1]), "+f"(d[2]), "+f"(d[3])
                 : "r"(a[0]), "r"(a[1]), "r"(a[2]), "r"(a[3]), "r"(b[0]), "r"(b[1]));
}
#define CP_ASYNC8(dst_u32, src_ptr, szreg) \
    asm volatile("cp.async.ca.shared.global [%0], [%1], 8, %2;" \
                 :: "r"(dst_u32), "l"(src_ptr), "r"(szreg))
#define CP_ASYNC16(dst_u32, src_ptr) \
    asm volatile("cp.async.cg.shared.global [%0], [%1], 16;" \
                 :: "r"(dst_u32), "l"(src_ptr))
#define CP_COMMIT() asm volatile("cp.async.commit_group;" ::: "memory")
#define CP_WAIT1() asm volatile("cp.async.wait_group 1;" ::: "memory")
#define CP_WAIT0() asm volatile("cp.async.wait_group 0;" ::: "memory")

// ------------------------- init -------------------------
__global__ void k_init() {
    int i = blockIdx.x * blockDim.x + threadIdx.x;
    if (i < NN) { g_degcnt[i] = 0; g_fill[i] = 0; g_tieflag[i] = 0; }
    if (i < 384) { g_gmax[i] = -3.402823466e38f; g_gsum[i] = 0.f; }
    if (i < 256) g_hist[i] = 0u;
    if (i == 0) { g_prefix = 0u; g_kprime = (unsigned)KKEEP; g_nties = 0; }
}

// ------------------------- B prep: split W[Kin,128] into fragment-major bf16 hi/lo ----
__global__ void k_prepB(const float *__restrict__ W, int Kin, int layer) {
    int i = blockIdx.x * blockDim.x + threadIdx.x;   // pair index
    if (i >= Kin * 64) return;
    int kp = i >> 7, n = i & 127;
    int k = kp * 2;
    float w0 = W[(size_t)k * 128 + n];
    float w1 = W[(size_t)(k + 1) * 128 + n];
    int c = k >> 5;
    int kk = k & 31;
    int nt = n >> 3, ks = kk >> 4;
    int r = ((kk & 15) >= 8) ? 1 : 0;
    int lane_b = (n & 7) * 4 + ((kk & 7) >> 1);
    int base = layer * 32768 + c * 2048 + ((nt * 2 + ks) * 32 + lane_b) * 2 + r;
    uint32_t h, l;
    split2_bf16(w0, w1, h, l);
    g_bhi[base] = h;
    g_blo[base] = l;
}

// ------------------------- degree / CSR build (edge_index is int32) -------------------------
__global__ void k_count(const int *__restrict__ ei) {
    int e4 = blockIdx.x * blockDim.x + threadIdx.x;
    if (e4 >= EE / 4) return;
    int4 d = *(const int4 *)&ei[EE + e4 * 4];
    atomicAdd(&g_degcnt[d.x], 1);
    atomicAdd(&g_degcnt[d.y], 1);
    atomicAdd(&g_degcnt[d.z], 1);
    atomicAdd(&g_degcnt[d.w], 1);
}
__global__ void k_chunksum() {
    __shared__ int sm[256];
    int t = threadIdx.x, b = blockIdx.x;
    int s = 0;
    for (int j = t; j < 1024; j += 256) {
        int idx = b * 1024 + j;
        if (idx < NN) s += g_degcnt[idx];
    }
    sm[t] = s; __syncthreads();
    for (int o = 128; o; o >>= 1) { if (t < o) sm[t] += sm[t + o]; __syncthreads(); }
    if (t == 0) g_chunksum[b] = sm[0];
}
__global__ void k_scanchunks() {
    int run = 0;
    for (int c = 0; c < NCH; ++c) { g_chunkoff[c] = run; run += g_chunksum[c]; }
    g_rowptr[NN] = EE;
}
__global__ void k_scanwrite() {
    __shared__ int sd[1024];
    int t = threadIdx.x, b = blockIdx.x;
    int idx = b * 1024 + t;
    int v = (idx < NN) ? g_degcnt[idx] : 0;
    int x = v;
    for (int o = 1; o < 1024; o <<= 1) {
        sd[t] = x; __syncthreads();
        if (t >= o) x += sd[t - o];
        __syncthreads();
    }
    if (idx < NN) g_rowptr[idx] = g_chunkoff[b] + x - v;
}
__global__ void k_scatter(const int *__restrict__ ei) {
    int e4 = blockIdx.x * blockDim.x + threadIdx.x;
    if (e4 >= EE / 4) return;
    int4 s = *(const int4 *)&ei[e4 * 4];
    int4 d = *(const int4 *)&ei[EE + e4 * 4];
    g_csr[g_rowptr[d.x] + atomicAdd(&g_fill[d.x], 1)] = s.x;
    g_csr[g_rowptr[d.y] + atomicAdd(&g_fill[d.y], 1)] = s.y;
    g_csr[g_rowptr[d.z] + atomicAdd(&g_fill[d.z], 1)] = s.z;
    g_csr[g_rowptr[d.w] + atomicAdd(&g_fill[d.w], 1)] = s.w;
}

// ------------------------- GEMM: cp.async pipeline carrying A (f32) + B hi/lo (bf16) ----
// y = ds*(X@W) stored as half2 pairs into g_yh.
#define GPIPE 3
#define GSTAGE 32768
#define GT_SMEM_BYTES (GPIPE * GSTAGE)
__global__ __launch_bounds__(256, 2) void k_gemm_mma(const float *__restrict__ Aext, int useExt,
                                                     int whichSrc, int Kin, int layer) {
    extern __shared__ char smem[];
    const float *A = useExt ? Aext : pickX(whichSrc);
    uint32_t sbase = (uint32_t)__cvta_generic_to_shared(smem);
    const uint32_t *bhi = g_bhi + layer * 32768;
    const uint32_t *blo = g_blo + layer * 32768;

    int tid = threadIdx.x, wid = tid >> 5, lane = tid & 31;
    int wm = wid & 3, wn = wid >> 2;
    int row0 = blockIdx.x * 128;

    int cp_m[8], cp_dst[8];
    const float *cp_src[8];
#pragma unroll
    for (int it = 0; it < 8; ++it) {
        int i = tid + it * 256;
        int m = i >> 4, p = i & 15;
        int mt = m >> 4, ks = p >> 3;
        int l = (m & 7) * 4 + (p & 3);
        int off = 2 * (((m & 15) >= 8) ? 1 : 0) + 4 * (((p & 7) >= 4) ? 1 : 0);
        int fidx = ((mt * 2 + ks) * 32 + l) * 8 + off;
        cp_m[it] = m;
        cp_dst[it] = fidx * 4;
        cp_src[it] = A + (size_t)(row0 + m) * Kin + p * 2;
    }

    float acc[2][8][4];
#pragma unroll
    for (int mt = 0; mt < 2; ++mt)
#pragma unroll
        for (int nt = 0; nt < 8; ++nt)
#pragma unroll
            for (int q = 0; q < 4; ++q) acc[mt][nt][q] = 0.f;

    int nchunks = Kin >> 5;

    auto issue = [&](int c, int buf) {
        uint32_t bb = sbase + buf * GSTAGE;
#pragma unroll
        for (int it = 0; it < 8; ++it) {
            int valid = (row0 + cp_m[it] < NN) ? 8 : 0;
            CP_ASYNC8(bb + cp_dst[it], cp_src[it] + c * 32, valid);
        }
#pragma unroll
        for (int j = 0; j < 2; ++j) {
            int idx = tid + j * 256;
            CP_ASYNC16(bb + 16384 + idx * 16, (const char *)&bhi[c * 2048 + idx * 4]);
            CP_ASYNC16(bb + 24576 + idx * 16, (const char *)&blo[c * 2048 + idx * 4]);
        }
    };

    issue(0, 0); CP_COMMIT();
    issue(1, 1); CP_COMMIT();

    for (int c = 0; c < nchunks; ++c) {
        if (c + 1 < nchunks) { CP_WAIT1(); } else { CP_WAIT0(); }
        __syncthreads();
        if (c + 2 < nchunks) { issue(c + 2, (c + 2) % GPIPE); CP_COMMIT(); }

        const char *stg = smem + (c % GPIPE) * GSTAGE;
        const float *fa = (const float *)stg;
        const uint32_t *fbh = (const uint32_t *)(stg + 16384);
        const uint32_t *fbl = (const uint32_t *)(stg + 24576);
#pragma unroll
        for (int ks = 0; ks < 2; ++ks) {
            uint32_t ah[2][4], al[2][4];
#pragma unroll
            for (int mt = 0; mt < 2; ++mt) {
                int mtg = wm * 2 + mt;
                const float4 *p4 = (const float4 *)&fa[((mtg * 2 + ks) * 32 + lane) * 8];
                float4 u = p4[0], v = p4[1];
                split2_bf16(u.x, u.y, ah[mt][0], al[mt][0]);
                split2_bf16(u.z, u.w, ah[mt][1], al[mt][1]);
                split2_bf16(v.x, v.y, ah[mt][2], al[mt][2]);
                split2_bf16(v.z, v.w, ah[mt][3], al[mt][3]);
            }
#pragma unroll
            for (int nt = 0; nt < 8; ++nt) {
                int ntg = wn * 8 + nt;
                int bidx = ((ntg * 2 + ks) * 32 + lane) * 2;
                uint2 vh = *(const uint2 *)&fbh[bidx];
                uint2 vl = *(const uint2 *)&fbl[bidx];
                uint32_t bh[2] = {vh.x, vh.y};
                uint32_t bl[2] = {vl.x, vl.y};
#pragma unroll
                for (int mt = 0; mt < 2; ++mt) {
                    mma16816(acc[mt][nt], ah[mt], bh);
                    mma16816(acc[mt][nt], ah[mt], bl);
                    mma16816(acc[mt][nt], al[mt], bh);
                }
            }
        }
    }

    // ---- epilogue: y = ds*acc stored as half2 into g_yh ----
    int r = lane >> 2;
#pragma unroll
    for (int mt = 0; mt < 2; ++mt) {
        int rbase = row0 + wm * 32 + mt * 16 + r;
#pragma unroll
        for (int half = 0; half < 2; ++half) {
            int row = rbase + half * 8;
            if (row >= NN) continue;
            float sc = rsqrtf((float)(g_degcnt[row] + 1));
            uint32_t *dst = &g_yh[(size_t)row * 64 + wn * 32 + (lane & 3)];
#pragma unroll
            for (int nt = 0; nt < 8; ++nt) {
                half2 h = __floats2half2_rn(acc[mt][nt][half * 2 + 0] * sc,
                                            acc[mt][nt][half * 2 + 1] * sc);
                dst[nt * 4] = *(uint32_t *)&h;
            }
        }
    }
}

// ------------------------- aggregation: out = relu(ds[d]*(sum_nb y + y[d]) + b) -------------------------
__global__ __launch_bounds__(256) void k_agg(const float *__restrict__ bias, int whichDst,
                                             int fuseScore, const float *__restrict__ Ws) {
    int gw = (blockIdx.x * 256 + threadIdx.x) >> 5;
    int lane = threadIdx.x & 31;
    if (gw >= NN) return;
    float *out = (float *)pickX(whichDst);
    int start = g_rowptr[gw], end = g_rowptr[gw + 1];
    int cu = lane * 2;
    uint2 sv = *(const uint2 *)&g_yh[(size_t)gw * 64 + cu];
    float2 s0 = __half22float2(*(half2 *)&sv.x);
    float2 s1 = __half22float2(*(half2 *)&sv.y);
    float4 acc = make_float4(s0.x, s0.y, s1.x, s1.y);  // self
    int e = start;
    for (; e + 4 <= end; e += 4) {
        int n0 = g_csr[e], n1 = g_csr[e + 1], n2 = g_csr[e + 2], n3 = g_csr[e + 3];
        uint2 v0 = *(const uint2 *)&g_yh[(size_t)n0 * 64 + cu];
        uint2 v1 = *(const uint2 *)&g_yh[(size_t)n1 * 64 + cu];
        uint2 v2 = *(const uint2 *)&g_yh[(size_t)n2 * 64 + cu];
        uint2 v3 = *(const uint2 *)&g_yh[(size_t)n3 * 64 + cu];
        float2 a0 = __half22float2(*(half2 *)&v0.x), b0 = __half22float2(*(half2 *)&v0.y);
        float2 a1 = __half22float2(*(half2 *)&v1.x), b1 = __half22float2(*(half2 *)&v1.y);
        float2 a2 = __half22float2(*(half2 *)&v2.x), b2 = __half22float2(*(half2 *)&v2.y);
        float2 a3 = __half22float2(*(half2 *)&v3.x), b3 = __half22float2(*(half2 *)&v3.y);
        acc.x += (a0.x + a1.x) + (a2.x + a3.x);
        acc.y += (a0.y + a1.y) + (a2.y + a3.y);
        acc.z += (b0.x + b1.x) + (b2.x + b3.x);
        acc.w += (b0.y + b1.y) + (b2.y + b3.y);
    }
    for (; e < end; ++e) {
        int n = g_csr[e];
        uint2 v = *(const uint2 *)&g_yh[(size_t)n * 64 + cu];
        float2 a = __half22float2(*(half2 *)&v.x), b = __half22float2(*(half2 *)&v.y);
        acc.x += a.x; acc.y += a.y; acc.z += b.x; acc.w += b.y;
    }
    float sc = rsqrtf((float)(g_degcnt[gw] + 1));
    int c0 = lane * 4;
    float4 b4 = *(const float4 *)&bias[c0];
    float4 o;
    o.x = fmaxf(fmaf(acc.x, sc, b4.x), 0.f);
    o.y = fmaxf(fmaf(acc.y, sc, b4.y), 0.f);
    o.z = fmaxf(fmaf(acc.z, sc, b4.z), 0.f);
    o.w = fmaxf(fmaf(acc.w, sc, b4.w), 0.f);
    *(float4 *)&out[(size_t)gw * 128 + c0] = o;

    if (fuseScore) {
        float4 w1 = *(const float4 *)&Ws[c0];
        float4 w2 = *(const float4 *)&Ws[128 + c0];
        float4 w3 = *(const float4 *)&Ws[256 + c0];
        float4 x1v = *(const float4 *)&g_x1[(size_t)gw * 128 + c0];
        float4 x2v = *(const float4 *)&g_x2[(size_t)gw * 128 + c0];
        float s = x1v.x * w1.x + x1v.y * w1.y + x1v.z * w1.z + x1v.w * w1.w
                + x2v.x * w2.x + x2v.y * w2.y + x2v.z * w2.z + x2v.w * w2.w
                + o.x * w3.x + o.y * w3.y + o.z * w3.z + o.w * w3.w;
        for (int off = 16; off; off >>= 1) s += __shfl_down_sync(0xFFFFFFFFu, s, off);
        if (lane == 0) g_ysc[gw] = sc * s;
    }
}

// ------------------------- score aggregate (scalar GCN) + fused radix pass-0 hist ----
__global__ __launch_bounds__(256) void k_score_agg(const float *__restrict__ bs) {
    int gw = (blockIdx.x * 256 + threadIdx.x) >> 5;
    int lane = threadIdx.x & 31;
    if (gw >= NN) return;
    int start = g_rowptr[gw], end = g_rowptr[gw + 1];
    float s = 0.f;
    for (int e = start + lane; e < end; e += 32) s += g_ysc[g_csr[e]];
    for (int o = 16; o; o >>= 1) s += __shfl_down_sync(0xFFFFFFFFu, s, o);
    if (lane == 0) {
        float tot = s + g_ysc[gw];
        float sc = fmaf(rsqrtf((float)(g_degcnt[gw] + 1)), tot, bs[0]);
        g_score[gw] = sc;
        unsigned k = fkey(sc);
        g_ukey[gw] = k;
        atomicAdd(&g_hist[k >> 24], 1u);   // fused radix pass-0 histogram
    }
}

// ------------------------- radix select (passes 1..3 of 8 bits) -------------------------
__global__ void k_hist(int pass) {
    __shared__ unsigned sh[256];
    int t = threadIdx.x;
    sh[t] = 0u; __syncthreads();
    int i = blockIdx.x * 256 + t;
    if (i < NN) {
        unsigned u = g_ukey[i];
        bool m = ((u >> (32 - 8 * pass)) == g_prefix);
        if (m) atomicAdd(&sh[(u >> (24 - 8 * pass)) & 255u], 1u);
    }
    __syncthreads();
    if (sh[t]) atomicAdd(&g_hist[t], sh[t]);
}
__global__ void k_select() {
    __shared__ unsigned h[256];
    int t = threadIdx.x;
    h[t] = g_hist[t];
    g_hist[t] = 0u;
    __syncthreads();
    if (t == 0) {
        unsigned kp = g_kprime, c = 0;
        int b;
        for (b = 255; b >= 0; --b) {
            if (c + h[b] >= kp) break;
            c += h[b];
        }
        if (b < 0) b = 0;
        g_prefix = (g_prefix << 8) | (unsigned)b;
        g_kprime = kp - c;
    }
}
__global__ void k_ties() {
    int i = blockIdx.x * blockDim.x + threadIdx.x;
    if (i >= NN) return;
    g_gate[i] = tanhf(g_score[i]);       // precompute pool gate (1 pass)
    if (g_ukey[i] == g_prefix) {
        int p = atomicAdd(&g_nties, 1);
        g_tieidx[p] = i;
    }
}
__global__ void k_tieresolve() {
    int M = g_nties;
    unsigned R = g_kprime;
    for (int j = threadIdx.x; j < M; j += blockDim.x) {
        int idx = g_tieidx[j];
        unsigned rank = 0;
        for (int l = 0; l < M; ++l) rank += (g_tieidx[l] < idx) ? 1u : 0u;
        if (rank < R) g_tieflag[idx] = 1;
    }
}

// ------------------------- pooling (max + sum over kept nodes, 384 dims) -------------------------
__global__ __launch_bounds__(384) void k_pool() {
    int c = threadIdx.x;
    const float *xa = (c < 128) ? g_x1 : ((c < 256) ? g_x2 : g_x3);
    int cc = c & 127;
    unsigned T = g_prefix;
    float mx = -3.402823466e38f, sm = 0.f;
    for (int i = blockIdx.x; i < NN; i += gridDim.x) {
        unsigned u = g_ukey[i];
        if (u < T) continue;
        if (u == T && !g_tieflag[i]) continue;
        float g = g_gate[i];
        float v = xa[(size_t)i * 128 + cc] * g;
        mx = fmaxf(mx, v);
        sm += v;
    }
    atomicMaxF(&g_gmax[c], mx);
    atomicAdd(&g_gsum[c], sm);
}

// ------------------------- final MLP head (single block) -------------------------
__global__ __launch_bounds__(128) void k_mlp(const float *__restrict__ Wl1, const float *__restrict__ bl1,
                                             const float *__restrict__ Wl2, const float *__restrict__ bl2,
                                             const float *__restrict__ Wl3, const float *__restrict__ bl3,
                                             float *__restrict__ out) {
    __shared__ float h[768], h1[128], h2[64], lg[10];
    int t = threadIdx.x;
    for (int c = t; c < 384; c += 128) {
        h[c] = g_gmax[c];
        h[384 + c] = g_gsum[c] * (1.0f / KKEEP);
    }
    __syncthreads();
    float s = bl1[t];
    for (int i = 0; i < 768; ++i) s = fmaf(h[i], Wl1[i * 128 + t], s);
    h1[t] = fmaxf(s, 0.f);
    __syncthreads();
    if (t < 64) {
        float s2 = bl2[t];
        for (int i = 0; i < 128; ++i) s2 = fmaf(h1[i], Wl2[i * 64 + t], s2);
        h2[t] = fmaxf(s2, 0.f);
    }
    __syncthreads();
    if (t < 10) {
        float s3 = bl3[t];
        for (int i = 0; i < 64; ++i) s3 = fmaf(h2[i], Wl3[i * 10 + t], s3);
        lg[t] = s3;
    }
    __syncthreads();
    if (t == 0) {
        float m = lg[0];
        for (int j = 1; j < 10; ++j) m = fmaxf(m, lg[j]);
        float se = 0.f;
        for (int j = 0; j < 10; ++j) se += expf(lg[j] - m);
        float lse = m + logf(se);
        for (int j = 0; j < 10; ++j) out[j] = lg[j] - lse;
    }
}

// ------------------------- launch -------------------------
extern "C" void kernel_launch(void *const *d_in, const int *in_sizes, int n_in,
                              void *d_out, int out_size) {
    const float *x      = (const float *)d_in[0];
    const int   *ei     = (const int *)d_in[1];   // int32
    const float *W1 = (const float *)d_in[3],  *b1  = (const float *)d_in[4];
    const float *W2 = (const float *)d_in[5],  *b2  = (const float *)d_in[6];
    const float *W3 = (const float *)d_in[7],  *b3  = (const float *)d_in[8];
    const float *Ws = (const float *)d_in[9],  *bs  = (const float *)d_in[10];
    const float *Wl1 = (const float *)d_in[11], *bl1 = (const float *)d_in[12];
    const float *Wl2 = (const float *)d_in[13], *bl2 = (const float *)d_in[14];
    const float *Wl3 = (const float *)d_in[15], *bl3 = (const float *)d_in[16];
    float *out = (float *)d_out;

    const int nblkN = (NN + 255) / 256;
    const int nblkE4 = (EE / 4 + 255) / 256;
    const int nblkW = (NN * 32 + 255) / 256;
    const int nblkT = (NN + 127) / 128;

    static cudaStream_t sCsr = nullptr, sPrep = nullptr;
    static cudaEvent_t evFork = nullptr, evCsr = nullptr, evPrep = nullptr;
    static bool inited = false;
    if (!inited) {
        cudaStreamCreateWithFlags(&sCsr, cudaStreamNonBlocking);
        cudaStreamCreateWithFlags(&sPrep, cudaStreamNonBlocking);
        cudaEventCreateWithFlags(&evFork, cudaEventDisableTiming);
        cudaEventCreateWithFlags(&evCsr, cudaEventDisableTiming);
        cudaEventCreateWithFlags(&evPrep, cudaEventDisableTiming);
        cudaFuncSetAttribute(k_gemm_mma, cudaFuncAttributeMaxDynamicSharedMemorySize, GT_SMEM_BYTES);
        inited = true;
    }

    // ---- origin stream: init, prepB layer0, degree count ----
    k_init<<<nblkN, 256>>>();
    k_prepB<<<(FIN * 64 + 255) / 256, 256>>>(W1, FIN, 0);
    k_count<<<nblkE4, 256>>>(ei);
    cudaEventRecord(evFork, 0);

    // ---- side stream 1: CSR build (overlaps GEMM-1) ----
    cudaStreamWaitEvent(sCsr, evFork, 0);
    k_chunksum<<<NCH, 256, 0, sCsr>>>();
    k_scanchunks<<<1, 1, 0, sCsr>>>();
    k_scanwrite<<<NCH, 1024, 0, sCsr>>>();
    k_scatter<<<nblkE4, 256, 0, sCsr>>>(ei);
    cudaEventRecord(evCsr, sCsr);

    // ---- side stream 2: prepB layers 1,2 ----
    cudaStreamWaitEvent(sPrep, evFork, 0);
    k_prepB<<<(HH * 64 + 255) / 256, 256, 0, sPrep>>>(W2, HH, 1);
    k_prepB<<<(HH * 64 + 255) / 256, 256, 0, sPrep>>>(W3, HH, 2);
    cudaEventRecord(evPrep, sPrep);

    // ---- origin: GCN layer 1 GEMM (concurrent with CSR build) ----
    k_gemm_mma<<<nblkT, 256, GT_SMEM_BYTES>>>(x, 1, 0, FIN, 0);
    cudaStreamWaitEvent(0, evCsr, 0);
    k_agg<<<nblkW, 256>>>(b1, 1, 0, nullptr);
    // layer 2
    cudaStreamWaitEvent(0, evPrep, 0);
    k_gemm_mma<<<nblkT, 256, GT_SMEM_BYTES>>>(nullptr, 0, 1, HH, 1);
    k_agg<<<nblkW, 256>>>(b2, 2, 0, nullptr);
    // layer 3 (+fused score linear)
    k_gemm_mma<<<nblkT, 256, GT_SMEM_BYTES>>>(nullptr, 0, 2, HH, 2);
    k_agg<<<nblkW, 256>>>(b3, 3, 1, Ws);
    // score aggregate (+fused radix pass-0 hist)
    k_score_agg<<<nblkW, 256>>>(bs);
    k_select<<<1, 256>>>();
    for (int p = 1; p < 4; ++p) {
        k_hist<<<nblkN, 256>>>(p);
        k_select<<<1, 256>>>();
    }
    k_ties<<<nblkN, 256>>>();
    k_tieresolve<<<1, 256>>>();
    // gated max/mean readout over kept nodes
    k_pool<<<512, 384>>>();
    // MLP head + log_softmax
    k_mlp<<<1, 128>>>(Wl1, bl1, Wl2, bl2, Wl3, bl3, out);
}

// round 14
// speedup vs baseline: 1.1131x; 1.0836x over previous
#include <cuda_runtime.h>
#include <cuda_fp16.h>
#include <math.h>
#include <stdint.h>

#define NN 100000
#define EE 1600000
#define FIN 512
#define HH 128
#define KKEEP 50000
#define NCH 98  // ceil(NN/1024)

typedef unsigned long long ull;

// ------------------------- device scratch (globals) -------------------------
__device__ __align__(16) uint32_t g_yh[(size_t)NN * 64];  // y = ds*(X@W) as half2 pairs
__device__ __align__(16) float g_x1[(size_t)NN * HH];
__device__ __align__(16) float g_x2[(size_t)NN * HH];
__device__ __align__(16) float g_x3[(size_t)NN * HH];
__device__ int   g_degcnt[NN];
__device__ int   g_rowptr[NN + 1];
__device__ int   g_fill[NN];
__device__ int   g_csr[EE];
__device__ int   g_chunksum[NCH];
__device__ int   g_chunkoff[NCH];
__device__ float g_ysc[NN];
__device__ float g_score[NN];
__device__ float g_gate[NN];
__device__ unsigned g_ukey[NN];
__device__ unsigned g_hist[256];
__device__ unsigned g_prefix;
__device__ unsigned g_kprime;
__device__ int   g_nties;
__device__ int   g_tieidx[NN];
__device__ int   g_tieflag[NN];
__device__ float g_gmax[384];
__device__ float g_gsum[384];
// pre-split B (W^T) fragments per layer, bf16 hi/lo, chunk-major: [layer][chunk][2048]
__device__ __align__(16) uint32_t g_bhi[3 * 16 * 2048];
__device__ __align__(16) uint32_t g_blo[3 * 16 * 2048];

// ------------------------- small helpers -------------------------
__device__ __forceinline__ unsigned fkey(float f) {
    unsigned u = __float_as_uint(f);
    return (u & 0x80000000u) ? ~u : (u | 0x80000000u);
}
__device__ __forceinline__ void atomicMaxF(float *addr, float val) {
    if (val >= 0.f) atomicMax((int *)addr, __float_as_int(val));
    else            atomicMin((unsigned *)addr, __float_as_uint(val));
}
__device__ __forceinline__ const float *pickX(int w) {
    return w == 1 ? g_x1 : (w == 2 ? g_x2 : g_x3);
}
__device__ __forceinline__ uint32_t pack_bf16x2(float x, float y) {
    uint32_t r;
    asm("cvt.rn.bf16x2.f32 %0, %1, %2;" : "=r"(r) : "f"(y), "f"(x));
    return r;
}
__device__ __forceinline__ float bf16lo_f(uint32_t p) { return __uint_as_float(p << 16); }
__device__ __forceinline__ float bf16hi_f(uint32_t p) { return __uint_as_float(p & 0xFFFF0000u); }
__device__ __forceinline__ void split2_bf16(float x, float y, uint32_t &hi, uint32_t &lo) {
    hi = pack_bf16x2(x, y);
    lo = pack_bf16x2(x - bf16lo_f(hi), y - bf16hi_f(hi));
}
__device__ __forceinline__ void mma16816(float *d, const uint32_t *a, const uint32_t *b) {
    asm volatile("mma.sync.aligned.m16n8k16.row.col.f32.bf16.bf16.f32 "
                 "{%0,%1,%2,%3}, {%4,%5,%6,%7}, {%8,%9}, {%0,%1,%2,%3};"
                 : "+f"(d[0]), "+f"(d[1]), "+f"(d[2]), "+f"(d[3])
                 : "r"(a[0]), "r"(a[1]), "r"(a[2]), "r"(a[3]), "r"(b[0]), "r"(b[1]));
}
#define CP_ASYNC8(dst_u32, src_ptr, szreg) \
    asm volatile("cp.async.ca.shared.global [%0], [%1], 8, %2;" \
                 :: "r"(dst_u32), "l"(src_ptr), "r"(szreg))
#define CP_ASYNC16(dst_u32, src_ptr) \
    asm volatile("cp.async.cg.shared.global [%0], [%1], 16;" \
                 :: "r"(dst_u32), "l"(src_ptr))
#define CP_COMMIT() asm volatile("cp.async.commit_group;" ::: "memory")
#define CP_WAIT1() asm volatile("cp.async.wait_group 1;" ::: "memory")
#define CP_WAIT0() asm volatile("cp.async.wait_group 0;" ::: "memory")

// ------------------------- init -------------------------
__global__ void k_init() {
    int i = blockIdx.x * blockDim.x + threadIdx.x;
    if (i < NN) { g_degcnt[i] = 0; g_fill[i] = 0; g_tieflag[i] = 0; }
    if (i < 384) { g_gmax[i] = -3.402823466e38f; g_gsum[i] = 0.f; }
    if (i < 256) g_hist[i] = 0u;
    if (i == 0) { g_prefix = 0u; g_kprime = (unsigned)KKEEP; g_nties = 0; }
}

// ------------------------- B prep: split W[Kin,128] into fragment-major bf16 hi/lo ----
__global__ void k_prepB(const float *__restrict__ W, int Kin, int layer) {
    int i = blockIdx.x * blockDim.x + threadIdx.x;   // pair index
    if (i >= Kin * 64) return;
    int kp = i >> 7, n = i & 127;
    int k = kp * 2;
    float w0 = W[(size_t)k * 128 + n];
    float w1 = W[(size_t)(k + 1) * 128 + n];
    int c = k >> 5;
    int kk = k & 31;
    int nt = n >> 3, ks = kk >> 4;
    int r = ((kk & 15) >= 8) ? 1 : 0;
    int lane_b = (n & 7) * 4 + ((kk & 7) >> 1);
    int base = layer * 32768 + c * 2048 + ((nt * 2 + ks) * 32 + lane_b) * 2 + r;
    uint32_t h, l;
    split2_bf16(w0, w1, h, l);
    g_bhi[base] = h;
    g_blo[base] = l;
}

// ------------------------- degree / CSR build (edge_index is int32) -------------------------
__global__ void k_count(const int *__restrict__ ei) {
    int e4 = blockIdx.x * blockDim.x + threadIdx.x;
    if (e4 >= EE / 4) return;
    int4 d = *(const int4 *)&ei[EE + e4 * 4];
    atomicAdd(&g_degcnt[d.x], 1);
    atomicAdd(&g_degcnt[d.y], 1);
    atomicAdd(&g_degcnt[d.z], 1);
    atomicAdd(&g_degcnt[d.w], 1);
}
__global__ void k_chunksum() {
    __shared__ int sm[256];
    int t = threadIdx.x, b = blockIdx.x;
    int s = 0;
    for (int j = t; j < 1024; j += 256) {
        int idx = b * 1024 + j;
        if (idx < NN) s += g_degcnt[idx];
    }
    sm[t] = s; __syncthreads();
    for (int o = 128; o; o >>= 1) { if (t < o) sm[t] += sm[t + o]; __syncthreads(); }
    if (t == 0) g_chunksum[b] = sm[0];
}
__global__ void k_scanchunks() {
    int run = 0;
    for (int c = 0; c < NCH; ++c) { g_chunkoff[c] = run; run += g_chunksum[c]; }
    g_rowptr[NN] = EE;
}
__global__ void k_scanwrite() {
    __shared__ int sd[1024];
    int t = threadIdx.x, b = blockIdx.x;
    int idx = b * 1024 + t;
    int v = (idx < NN) ? g_degcnt[idx] : 0;
    int x = v;
    for (int o = 1; o < 1024; o <<= 1) {
        sd[t] = x; __syncthreads();
        if (t >= o) x += sd[t - o];
        __syncthreads();
    }
    if (idx < NN) g_rowptr[idx] = g_chunkoff[b] + x - v;
}
__global__ void k_scatter(const int *__restrict__ ei) {
    int e4 = blockIdx.x * blockDim.x + threadIdx.x;
    if (e4 >= EE / 4) return;
    int4 s = *(const int4 *)&ei[e4 * 4];
    int4 d = *(const int4 *)&ei[EE + e4 * 4];
    g_csr[g_rowptr[d.x] + atomicAdd(&g_fill[d.x], 1)] = s.x;
    g_csr[g_rowptr[d.y] + atomicAdd(&g_fill[d.y], 1)] = s.y;
    g_csr[g_rowptr[d.z] + atomicAdd(&g_fill[d.z], 1)] = s.z;
    g_csr[g_rowptr[d.w] + atomicAdd(&g_fill[d.w], 1)] = s.w;
}

// ------------------------- GEMM: cp.async pipeline carrying A (f32) + B hi/lo (bf16) ----
// y = ds*(X@W) stored as half2 pairs into g_yh.
#define GPIPE 3
#define GSTAGE 32768
#define GT_SMEM_BYTES (GPIPE * GSTAGE)
__global__ __launch_bounds__(256, 2) void k_gemm_mma(const float *__restrict__ Aext, int useExt,
                                                     int whichSrc, int Kin, int layer) {
    extern __shared__ char smem[];
    const float *A = useExt ? Aext : pickX(whichSrc);
    uint32_t sbase = (uint32_t)__cvta_generic_to_shared(smem);
    const uint32_t *bhi = g_bhi + layer * 32768;
    const uint32_t *blo = g_blo + layer * 32768;

    int tid = threadIdx.x, wid = tid >> 5, lane = tid & 31;
    int wm = wid & 3, wn = wid >> 2;
    int row0 = blockIdx.x * 128;

    int cp_m[8], cp_dst[8];
    const float *cp_src[8];
#pragma unroll
    for (int it = 0; it < 8; ++it) {
        int i = tid + it * 256;
        int m = i >> 4, p = i & 15;
        int mt = m >> 4, ks = p >> 3;
        int l = (m & 7) * 4 + (p & 3);
        int off = 2 * (((m & 15) >= 8) ? 1 : 0) + 4 * (((p & 7) >= 4) ? 1 : 0);
        int fidx = ((mt * 2 + ks) * 32 + l) * 8 + off;
        cp_m[it] = m;
        cp_dst[it] = fidx * 4;
        cp_src[it] = A + (size_t)(row0 + m) * Kin + p * 2;
    }

    float acc[2][8][4];
#pragma unroll
    for (int mt = 0; mt < 2; ++mt)
#pragma unroll
        for (int nt = 0; nt < 8; ++nt)
#pragma unroll
            for (int q = 0; q < 4; ++q) acc[mt][nt][q] = 0.f;

    int nchunks = Kin >> 5;

    auto issue = [&](int c, int buf) {
        uint32_t bb = sbase + buf * GSTAGE;
#pragma unroll
        for (int it = 0; it < 8; ++it) {
            int valid = (row0 + cp_m[it] < NN) ? 8 : 0;
            CP_ASYNC8(bb + cp_dst[it], cp_src[it] + c * 32, valid);
        }
#pragma unroll
        for (int j = 0; j < 2; ++j) {
            int idx = tid + j * 256;
            CP_ASYNC16(bb + 16384 + idx * 16, (const char *)&bhi[c * 2048 + idx * 4]);
            CP_ASYNC16(bb + 24576 + idx * 16, (const char *)&blo[c * 2048 + idx * 4]);
        }
    };

    issue(0, 0); CP_COMMIT();
    issue(1, 1); CP_COMMIT();

    for (int c = 0; c < nchunks; ++c) {
        if (c + 1 < nchunks) { CP_WAIT1(); } else { CP_WAIT0(); }
        __syncthreads();
        if (c + 2 < nchunks) { issue(c + 2, (c + 2) % GPIPE); CP_COMMIT(); }

        const char *stg = smem + (c % GPIPE) * GSTAGE;
        const float *fa = (const float *)stg;
        const uint32_t *fbh = (const uint32_t *)(stg + 16384);
        const uint32_t *fbl = (const uint32_t *)(stg + 24576);
#pragma unroll
        for (int ks = 0; ks < 2; ++ks) {
            uint32_t ah[2][4], al[2][4];
#pragma unroll
            for (int mt = 0; mt < 2; ++mt) {
                int mtg = wm * 2 + mt;
                const float4 *p4 = (const float4 *)&fa[((mtg * 2 + ks) * 32 + lane) * 8];
                float4 u = p4[0], v = p4[1];
                split2_bf16(u.x, u.y, ah[mt][0], al[mt][0]);
                split2_bf16(u.z, u.w, ah[mt][1], al[mt][1]);
                split2_bf16(v.x, v.y, ah[mt][2], al[mt][2]);
                split2_bf16(v.z, v.w, ah[mt][3], al[mt][3]);
            }
#pragma unroll
            for (int nt = 0; nt < 8; ++nt) {
                int ntg = wn * 8 + nt;
                int bidx = ((ntg * 2 + ks) * 32 + lane) * 2;
                uint2 vh = *(const uint2 *)&fbh[bidx];
                uint2 vl = *(const uint2 *)&fbl[bidx];
                uint32_t bh[2] = {vh.x, vh.y};
                uint32_t bl[2] = {vl.x, vl.y};
#pragma unroll
                for (int mt = 0; mt < 2; ++mt) {
                    mma16816(acc[mt][nt], ah[mt], bh);
                    mma16816(acc[mt][nt], ah[mt], bl);
                    mma16816(acc[mt][nt], al[mt], bh);
                }
            }
        }
    }

    // ---- epilogue: y = ds*acc stored as half2 into g_yh ----
    int r = lane >> 2;
#pragma unroll
    for (int mt = 0; mt < 2; ++mt) {
        int rbase = row0 + wm * 32 + mt * 16 + r;
#pragma unroll
        for (int half = 0; half < 2; ++half) {
            int row = rbase + half * 8;
            if (row >= NN) continue;
            float sc = rsqrtf((float)(g_degcnt[row] + 1));
            uint32_t *dst = &g_yh[(size_t)row * 64 + wn * 32 + (lane & 3)];
#pragma unroll
            for (int nt = 0; nt < 8; ++nt) {
                half2 h = __floats2half2_rn(acc[mt][nt][half * 2 + 0] * sc,
                                            acc[mt][nt][half * 2 + 1] * sc);
                dst[nt * 4] = *(uint32_t *)&h;
            }
        }
    }
}

// ------------------------- aggregation: out = relu(ds[d]*(sum_nb y + y[d]) + b) -------------------------
__global__ __launch_bounds__(256) void k_agg(const float *__restrict__ bias, int whichDst,
                                             int fuseScore, const float *__restrict__ Ws) {
    int gw = (blockIdx.x * 256 + threadIdx.x) >> 5;
    int lane = threadIdx.x & 31;
    if (gw >= NN) return;
    float *out = (float *)pickX(whichDst);
    int start = g_rowptr[gw], end = g_rowptr[gw + 1];
    int cu = lane * 2;
    uint2 sv = *(const uint2 *)&g_yh[(size_t)gw * 64 + cu];
    float2 s0 = __half22float2(*(half2 *)&sv.x);
    float2 s1 = __half22float2(*(half2 *)&sv.y);
    float4 acc = make_float4(s0.x, s0.y, s1.x, s1.y);  // self
    int e = start;
    for (; e + 4 <= end; e += 4) {
        int n0 = g_csr[e], n1 = g_csr[e + 1], n2 = g_csr[e + 2], n3 = g_csr[e + 3];
        uint2 v0 = *(const uint2 *)&g_yh[(size_t)n0 * 64 + cu];
        uint2 v1 = *(const uint2 *)&g_yh[(size_t)n1 * 64 + cu];
        uint2 v2 = *(const uint2 *)&g_yh[(size_t)n2 * 64 + cu];
        uint2 v3 = *(const uint2 *)&g_yh[(size_t)n3 * 64 + cu];
        float2 a0 = __half22float2(*(half2 *)&v0.x), b0 = __half22float2(*(half2 *)&v0.y);
        float2 a1 = __half22float2(*(half2 *)&v1.x), b1 = __half22float2(*(half2 *)&v1.y);
        float2 a2 = __half22float2(*(half2 *)&v2.x), b2 = __half22float2(*(half2 *)&v2.y);
        float2 a3 = __half22float2(*(half2 *)&v3.x), b3 = __half22float2(*(half2 *)&v3.y);
        acc.x += (a0.x + a1.x) + (a2.x + a3.x);
        acc.y += (a0.y + a1.y) + (a2.y + a3.y);
        acc.z += (b0.x + b1.x) + (b2.x + b3.x);
        acc.w += (b0.y + b1.y) + (b2.y + b3.y);
    }
    for (; e < end; ++e) {
        int n = g_csr[e];
        uint2 v = *(const uint2 *)&g_yh[(size_t)n * 64 + cu];
        float2 a = __half22float2(*(half2 *)&v.x), b = __half22float2(*(half2 *)&v.y);
        acc.x += a.x; acc.y += a.y; acc.z += b.x; acc.w += b.y;
    }
    float sc = rsqrtf((float)(g_degcnt[gw] + 1));
    int c0 = lane * 4;
    float4 b4 = *(const float4 *)&bias[c0];
    float4 o;
    o.x = fmaxf(fmaf(acc.x, sc, b4.x), 0.f);
    o.y = fmaxf(fmaf(acc.y, sc, b4.y), 0.f);
    o.z = fmaxf(fmaf(acc.z, sc, b4.z), 0.f);
    o.w = fmaxf(fmaf(acc.w, sc, b4.w), 0.f);
    *(float4 *)&out[(size_t)gw * 128 + c0] = o;

    if (fuseScore) {
        float4 w1 = *(const float4 *)&Ws[c0];
        float4 w2 = *(const float4 *)&Ws[128 + c0];
        float4 w3 = *(const float4 *)&Ws[256 + c0];
        float4 x1v = *(const float4 *)&g_x1[(size_t)gw * 128 + c0];
        float4 x2v = *(const float4 *)&g_x2[(size_t)gw * 128 + c0];
        float s = x1v.x * w1.x + x1v.y * w1.y + x1v.z * w1.z + x1v.w * w1.w
                + x2v.x * w2.x + x2v.y * w2.y + x2v.z * w2.z + x2v.w * w2.w
                + o.x * w3.x + o.y * w3.y + o.z * w3.z + o.w * w3.w;
        for (int off = 16; off; off >>= 1) s += __shfl_down_sync(0xFFFFFFFFu, s, off);
        if (lane == 0) g_ysc[gw] = sc * s;
    }
}

// ------------------------- score aggregate (scalar GCN) -------------------------
__global__ __launch_bounds__(256) void k_score_agg(const float *__restrict__ bs) {
    int gw = (blockIdx.x * 256 + threadIdx.x) >> 5;
    int lane = threadIdx.x & 31;
    if (gw >= NN) return;
    int start = g_rowptr[gw], end = g_rowptr[gw + 1];
    float s = 0.f;
    for (int e = start + lane; e < end; e += 32) s += g_ysc[g_csr[e]];
    for (int o = 16; o; o >>= 1) s += __shfl_down_sync(0xFFFFFFFFu, s, o);
    if (lane == 0) {
        float tot = s + g_ysc[gw];
        float sc = fmaf(rsqrtf((float)(g_degcnt[gw] + 1)), tot, bs[0]);
        g_score[gw] = sc;
        g_ukey[gw] = fkey(sc);
    }
}

// ------------------------- radix select (4 passes of 8 bits) -------------------------
__global__ void k_hist(int pass) {
    __shared__ unsigned sh[256];
    int t = threadIdx.x;
    sh[t] = 0u; __syncthreads();
    int i = blockIdx.x * 256 + t;
    if (i < NN) {
        unsigned u = g_ukey[i];
        bool m = (pass == 0) || ((u >> (32 - 8 * pass)) == g_prefix);
        if (m) atomicAdd(&sh[(u >> (24 - 8 * pass)) & 255u], 1u);
    }
    __syncthreads();
    if (sh[t]) atomicAdd(&g_hist[t], sh[t]);
}
__global__ void k_select() {
    __shared__ unsigned h[256];
    int t = threadIdx.x;
    h[t] = g_hist[t];
    g_hist[t] = 0u;
    __syncthreads();
    if (t == 0) {
        unsigned kp = g_kprime, c = 0;
        int b;
        for (b = 255; b >= 0; --b) {
            if (c + h[b] >= kp) break;
            c += h[b];
        }
        if (b < 0) b = 0;
        g_prefix = (g_prefix << 8) | (unsigned)b;
        g_kprime = kp - c;
    }
}
__global__ void k_ties() {
    int i = blockIdx.x * blockDim.x + threadIdx.x;
    if (i >= NN) return;
    g_gate[i] = tanhf(g_score[i]);       // precompute pool gate (single pass)
    if (g_ukey[i] == g_prefix) {
        int p = atomicAdd(&g_nties, 1);
        g_tieidx[p] = i;
    }
}
__global__ void k_tieresolve() {
    int M = g_nties;
    unsigned R = g_kprime;
    for (int j = threadIdx.x; j < M; j += blockDim.x) {
        int idx = g_tieidx[j];
        unsigned rank = 0;
        for (int l = 0; l < M; ++l) rank += (g_tieidx[l] < idx) ? 1u : 0u;
        if (rank < R) g_tieflag[idx] = 1;
    }
}

// ------------------------- pooling (max + sum over kept nodes, 384 dims) -------------------------
__global__ __launch_bounds__(384) void k_pool() {
    int c = threadIdx.x;
    const float *xa = (c < 128) ? g_x1 : ((c < 256) ? g_x2 : g_x3);
    int cc = c & 127;
    unsigned T = g_prefix;
    float mx = -3.402823466e38f, sm = 0.f;
    for (int i = blockIdx.x; i < NN; i += gridDim.x) {
        unsigned u = g_ukey[i];
        if (u < T) continue;
        if (u == T && !g_tieflag[i]) continue;
        float g = g_gate[i];
        float v = xa[(size_t)i * 128 + cc] * g;
        mx = fmaxf(mx, v);
        sm += v;
    }
    atomicMaxF(&g_gmax[c], mx);
    atomicAdd(&g_gsum[c], sm);
}

// ------------------------- final MLP head (single block) -------------------------
__global__ __launch_bounds__(128) void k_mlp(const float *__restrict__ Wl1, const float *__restrict__ bl1,
                                             const float *__restrict__ Wl2, const float *__restrict__ bl2,
                                             const float *__restrict__ Wl3, const float *__restrict__ bl3,
                                             float *__restrict__ out) {
    __shared__ float h[768], h1[128], h2[64], lg[10];
    int t = threadIdx.x;
    for (int c = t; c < 384; c += 128) {
        h[c] = g_gmax[c];
        h[384 + c] = g_gsum[c] * (1.0f / KKEEP);
    }
    __syncthreads();
    float s = bl1[t];
    for (int i = 0; i < 768; ++i) s = fmaf(h[i], Wl1[i * 128 + t], s);
    h1[t] = fmaxf(s, 0.f);
    __syncthreads();
    if (t < 64) {
        float s2 = bl2[t];
        for (int i = 0; i < 128; ++i) s2 = fmaf(h1[i], Wl2[i * 64 + t], s2);
        h2[t] = fmaxf(s2, 0.f);
    }
    __syncthreads();
    if (t < 10) {
        float s3 = bl3[t];
        for (int i = 0; i < 64; ++i) s3 = fmaf(h2[i], Wl3[i * 10 + t], s3);
        lg[t] = s3;
    }
    __syncthreads();
    if (t == 0) {
        float m = lg[0];
        for (int j = 1; j < 10; ++j) m = fmaxf(m, lg[j]);
        float se = 0.f;
        for (int j = 0; j < 10; ++j) se += expf(lg[j] - m);
        float lse = m + logf(se);
        for (int j = 0; j < 10; ++j) out[j] = lg[j] - lse;
    }
}

// ------------------------- launch -------------------------
extern "C" void kernel_launch(void *const *d_in, const int *in_sizes, int n_in,
                              void *d_out, int out_size) {
    const float *x      = (const float *)d_in[0];
    const int   *ei     = (const int *)d_in[1];   // int32
    const float *W1 = (const float *)d_in[3],  *b1  = (const float *)d_in[4];
    const float *W2 = (const float *)d_in[5],  *b2  = (const float *)d_in[6];
    const float *W3 = (const float *)d_in[7],  *b3  = (const float *)d_in[8];
    const float *Ws = (const float *)d_in[9],  *bs  = (const float *)d_in[10];
    const float *Wl1 = (const float *)d_in[11], *bl1 = (const float *)d_in[12];
    const float *Wl2 = (const float *)d_in[13], *bl2 = (const float *)d_in[14];
    const float *Wl3 = (const float *)d_in[15], *bl3 = (const float *)d_in[16];
    float *out = (float *)d_out;

    const int nblkN = (NN + 255) / 256;
    const int nblkE4 = (EE / 4 + 255) / 256;
    const int nblkW = (NN * 32 + 255) / 256;
    const int nblkT = (NN + 127) / 128;

    static cudaStream_t sCsr = nullptr, sPrep = nullptr;
    static cudaEvent_t evFork = nullptr, evCsr = nullptr, evPrep = nullptr;
    static bool inited = false;
    if (!inited) {
        cudaStreamCreateWithFlags(&sCsr, cudaStreamNonBlocking);
        cudaStreamCreateWithFlags(&sPrep, cudaStreamNonBlocking);
        cudaEventCreateWithFlags(&evFork, cudaEventDisableTiming);
        cudaEventCreateWithFlags(&evCsr, cudaEventDisableTiming);
        cudaEventCreateWithFlags(&evPrep, cudaEventDisableTiming);
        cudaFuncSetAttribute(k_gemm_mma, cudaFuncAttributeMaxDynamicSharedMemorySize, GT_SMEM_BYTES);
        inited = true;
    }

    // ---- origin stream: init, prepB layer0, degree count ----
    k_init<<<nblkN, 256>>>();
    k_prepB<<<(FIN * 64 + 255) / 256, 256>>>(W1, FIN, 0);
    k_count<<<nblkE4, 256>>>(ei);
    cudaEventRecord(evFork, 0);

    // ---- side stream 1: CSR build (overlaps GEMM-1) ----
    cudaStreamWaitEvent(sCsr, evFork, 0);
    k_chunksum<<<NCH, 256, 0, sCsr>>>();
    k_scanchunks<<<1, 1, 0, sCsr>>>();
    k_scanwrite<<<NCH, 1024, 0, sCsr>>>();
    k_scatter<<<nblkE4, 256, 0, sCsr>>>(ei);
    cudaEventRecord(evCsr, sCsr);

    // ---- side stream 2: prepB layers 1,2 ----
    cudaStreamWaitEvent(sPrep, evFork, 0);
    k_prepB<<<(HH * 64 + 255) / 256, 256, 0, sPrep>>>(W2, HH, 1);
    k_prepB<<<(HH * 64 + 255) / 256, 256, 0, sPrep>>>(W3, HH, 2);
    cudaEventRecord(evPrep, sPrep);

    // ---- origin: GCN layer 1 GEMM (concurrent with CSR build) ----
    k_gemm_mma<<<nblkT, 256, GT_SMEM_BYTES>>>(x, 1, 0, FIN, 0);
    cudaStreamWaitEvent(0, evCsr, 0);
    k_agg<<<nblkW, 256>>>(b1, 1, 0, nullptr);
    // layer 2
    cudaStreamWaitEvent(0, evPrep, 0);
    k_gemm_mma<<<nblkT, 256, GT_SMEM_BYTES>>>(nullptr, 0, 1, HH, 1);
    k_agg<<<nblkW, 256>>>(b2, 2, 0, nullptr);
    // layer 3 (+fused score linear)
    k_gemm_mma<<<nblkT, 256, GT_SMEM_BYTES>>>(nullptr, 0, 2, HH, 2);
    k_agg<<<nblkW, 256>>>(b3, 3, 1, Ws);
    // score aggregate
    k_score_agg<<<nblkW, 256>>>(bs);
    // exact top-k threshold via 4x8-bit radix select
    for (int p = 0; p < 4; ++p) {
        k_hist<<<nblkN, 256>>>(p);
        k_select<<<1, 256>>>();
    }
    k_ties<<<nblkN, 256>>>();
    k_tieresolve<<<1, 256>>>();
    // gated max/mean readout over kept nodes
    k_pool<<<512, 384>>>();
    // MLP head + log_softmax
    k_mlp<<<1, 128>>>(Wl1, bl1, Wl2, bl2, Wl3, bl3, out);
}

// round 15
// speedup vs baseline: 1.1137x; 1.0006x over previous
#include <cuda_runtime.h>
#include <cuda_fp16.h>
#include <math.h>
#include <stdint.h>

#define NN 100000
#define EE 1600000
#define FIN 512
#define HH 128
#define KKEEP 50000
#define NCH 98   // ceil(NN/1024)
#define RBLK 391 // ceil(NN/256) persistent blocks for radix megakernel

typedef unsigned long long ull;

// ------------------------- device scratch (globals) -------------------------
__device__ __align__(16) uint32_t g_yh[(size_t)NN * 64];  // y = ds*(X@W) as half2 pairs
__device__ __align__(16) float g_x1[(size_t)NN * HH];
__device__ __align__(16) float g_x2[(size_t)NN * HH];
__device__ __align__(16) float g_x3[(size_t)NN * HH];
__device__ int   g_degcnt[NN];
__device__ int   g_rowptr[NN + 1];
__device__ int   g_fill[NN];
__device__ int   g_csr[EE];
__device__ int   g_chunksum[NCH];
__device__ int   g_chunkoff[NCH];
__device__ float g_ysc[NN];
__device__ float g_score[NN];
__device__ float g_gate[NN];
__device__ unsigned g_ukey[NN];
__device__ unsigned g_hist4[4 * 256];
__device__ unsigned g_barcnt;
__device__ unsigned g_prefix;
__device__ int   g_nties;
__device__ int   g_tieidx[NN];
__device__ int   g_tieflag[NN];
__device__ float g_gmax[384];
__device__ float g_gsum[384];
// pre-split B (W^T) fragments per layer, bf16 hi/lo, chunk-major: [layer][chunk][2048]
__device__ __align__(16) uint32_t g_bhi[3 * 16 * 2048];
__device__ __align__(16) uint32_t g_blo[3 * 16 * 2048];

// ------------------------- small helpers -------------------------
__device__ __forceinline__ unsigned fkey(float f) {
    unsigned u = __float_as_uint(f);
    return (u & 0x80000000u) ? ~u : (u | 0x80000000u);
}
__device__ __forceinline__ void atomicMaxF(float *addr, float val) {
    if (val >= 0.f) atomicMax((int *)addr, __float_as_int(val));
    else            atomicMin((unsigned *)addr, __float_as_uint(val));
}
__device__ __forceinline__ const float *pickX(int w) {
    return w == 1 ? g_x1 : (w == 2 ? g_x2 : g_x3);
}
__device__ __forceinline__ uint32_t pack_bf16x2(float x, float y) {
    uint32_t r;
    asm("cvt.rn.bf16x2.f32 %0, %1, %2;" : "=r"(r) : "f"(y), "f"(x));
    return r;
}
__device__ __forceinline__ float bf16lo_f(uint32_t p) { return __uint_as_float(p << 16); }
__device__ __forceinline__ float bf16hi_f(uint32_t p) { return __uint_as_float(p & 0xFFFF0000u); }
__device__ __forceinline__ void split2_bf16(float x, float y, uint32_t &hi, uint32_t &lo) {
    hi = pack_bf16x2(x, y);
    lo = pack_bf16x2(x - bf16lo_f(hi), y - bf16hi_f(hi));
}
__device__ __forceinline__ void mma16816(float *d, const uint32_t *a, const uint32_t *b) {
    asm volatile("mma.sync.aligned.m16n8k16.row.col.f32.bf16.bf16.f32 "
                 "{%0,%1,%2,%3}, {%4,%5,%6,%7}, {%8,%9}, {%0,%1,%2,%3};"
                 : "+f"(d[0]), "+f"(d[1]), "+f"(d[2]), "+f"(d[3])
                 : "r"(a[0]), "r"(a[1]), "r"(a[2]), "r"(a[3]), "r"(b[0]), "r"(b[1]));
}
#define CP_ASYNC8(dst_u32, src_ptr, szreg) \
    asm volatile("cp.async.ca.shared.global [%0], [%1], 8, %2;" \
                 :: "r"(dst_u32), "l"(src_ptr), "r"(szreg))
#define CP_ASYNC16(dst_u32, src_ptr) \
    asm volatile("cp.async.cg.shared.global [%0], [%1], 16;" \
                 :: "r"(dst_u32), "l"(src_ptr))
#define CP_COMMIT() asm volatile("cp.async.commit_group;" ::: "memory")
#define CP_WAIT1() asm volatile("cp.async.wait_group 1;" ::: "memory")
#define CP_WAIT0() asm volatile("cp.async.wait_group 0;" ::: "memory")

// ------------------------- init -------------------------
__global__ void k_init() {
    int i = blockIdx.x * blockDim.x + threadIdx.x;
    if (i < NN) { g_degcnt[i] = 0; g_fill[i] = 0; g_tieflag[i] = 0; }
    if (i < 384) { g_gmax[i] = -3.402823466e38f; g_gsum[i] = 0.f; }
    if (i < 1024) g_hist4[i] = 0u;
    if (i == 0) { g_barcnt = 0u; g_nties = 0; }
}

// ------------------------- B prep: split W[Kin,128] into fragment-major bf16 hi/lo ----
__global__ void k_prepB(const float *__restrict__ W, int Kin, int layer) {
    int i = blockIdx.x * blockDim.x + threadIdx.x;   // pair index
    if (i >= Kin * 64) return;
    int kp = i >> 7, n = i & 127;
    int k = kp * 2;
    float w0 = W[(size_t)k * 128 + n];
    float w1 = W[(size_t)(k + 1) * 128 + n];
    int c = k >> 5;
    int kk = k & 31;
    int nt = n >> 3, ks = kk >> 4;
    int r = ((kk & 15) >= 8) ? 1 : 0;
    int lane_b = (n & 7) * 4 + ((kk & 7) >> 1);
    int base = layer * 32768 + c * 2048 + ((nt * 2 + ks) * 32 + lane_b) * 2 + r;
    uint32_t h, l;
    split2_bf16(w0, w1, h, l);
    g_bhi[base] = h;
    g_blo[base] = l;
}

// ------------------------- degree / CSR build (edge_index is int32) -------------------------
__global__ void k_count(const int *__restrict__ ei) {
    int e4 = blockIdx.x * blockDim.x + threadIdx.x;
    if (e4 >= EE / 4) return;
    int4 d = *(const int4 *)&ei[EE + e4 * 4];
    atomicAdd(&g_degcnt[d.x], 1);
    atomicAdd(&g_degcnt[d.y], 1);
    atomicAdd(&g_degcnt[d.z], 1);
    atomicAdd(&g_degcnt[d.w], 1);
}
__global__ void k_chunksum() {
    __shared__ int sm[256];
    int t = threadIdx.x, b = blockIdx.x;
    int s = 0;
    for (int j = t; j < 1024; j += 256) {
        int idx = b * 1024 + j;
        if (idx < NN) s += g_degcnt[idx];
    }
    sm[t] = s; __syncthreads();
    for (int o = 128; o; o >>= 1) { if (t < o) sm[t] += sm[t + o]; __syncthreads(); }
    if (t == 0) g_chunksum[b] = sm[0];
}
__global__ void k_scanchunks() {
    int run = 0;
    for (int c = 0; c < NCH; ++c) { g_chunkoff[c] = run; run += g_chunksum[c]; }
    g_rowptr[NN] = EE;
}
__global__ void k_scanwrite() {
    __shared__ int sd[1024];
    int t = threadIdx.x, b = blockIdx.x;
    int idx = b * 1024 + t;
    int v = (idx < NN) ? g_degcnt[idx] : 0;
    int x = v;
    for (int o = 1; o < 1024; o <<= 1) {
        sd[t] = x; __syncthreads();
        if (t >= o) x += sd[t - o];
        __syncthreads();
    }
    if (idx < NN) g_rowptr[idx] = g_chunkoff[b] + x - v;
}
__global__ void k_scatter(const int *__restrict__ ei) {
    int e4 = blockIdx.x * blockDim.x + threadIdx.x;
    if (e4 >= EE / 4) return;
    int4 s = *(const int4 *)&ei[e4 * 4];
    int4 d = *(const int4 *)&ei[EE + e4 * 4];
    g_csr[g_rowptr[d.x] + atomicAdd(&g_fill[d.x], 1)] = s.x;
    g_csr[g_rowptr[d.y] + atomicAdd(&g_fill[d.y], 1)] = s.y;
    g_csr[g_rowptr[d.z] + atomicAdd(&g_fill[d.z], 1)] = s.z;
    g_csr[g_rowptr[d.w] + atomicAdd(&g_fill[d.w], 1)] = s.w;
}

// ------------------------- GEMM: cp.async pipeline carrying A (f32) + B hi/lo (bf16) ----
// y = ds*(X@W) stored as half2 pairs into g_yh.
#define GPIPE 3
#define GSTAGE 32768
#define GT_SMEM_BYTES (GPIPE * GSTAGE)
__global__ __launch_bounds__(256, 2) void k_gemm_mma(const float *__restrict__ Aext, int useExt,
                                                     int whichSrc, int Kin, int layer) {
    extern __shared__ char smem[];
    const float *A = useExt ? Aext : pickX(whichSrc);
    uint32_t sbase = (uint32_t)__cvta_generic_to_shared(smem);
    const uint32_t *bhi = g_bhi + layer * 32768;
    const uint32_t *blo = g_blo + layer * 32768;

    int tid = threadIdx.x, wid = tid >> 5, lane = tid & 31;
    int wm = wid & 3, wn = wid >> 2;
    int row0 = blockIdx.x * 128;

    int cp_m[8], cp_dst[8];
    const float *cp_src[8];
#pragma unroll
    for (int it = 0; it < 8; ++it) {
        int i = tid + it * 256;
        int m = i >> 4, p = i & 15;
        int mt = m >> 4, ks = p >> 3;
        int l = (m & 7) * 4 + (p & 3);
        int off = 2 * (((m & 15) >= 8) ? 1 : 0) + 4 * (((p & 7) >= 4) ? 1 : 0);
        int fidx = ((mt * 2 + ks) * 32 + l) * 8 + off;
        cp_m[it] = m;
        cp_dst[it] = fidx * 4;
        cp_src[it] = A + (size_t)(row0 + m) * Kin + p * 2;
    }

    float acc[2][8][4];
#pragma unroll
    for (int mt = 0; mt < 2; ++mt)
#pragma unroll
        for (int nt = 0; nt < 8; ++nt)
#pragma unroll
            for (int q = 0; q < 4; ++q) acc[mt][nt][q] = 0.f;

    int nchunks = Kin >> 5;

    auto issue = [&](int c, int buf) {
        uint32_t bb = sbase + buf * GSTAGE;
#pragma unroll
        for (int it = 0; it < 8; ++it) {
            int valid = (row0 + cp_m[it] < NN) ? 8 : 0;
            CP_ASYNC8(bb + cp_dst[it], cp_src[it] + c * 32, valid);
        }
#pragma unroll
        for (int j = 0; j < 2; ++j) {
            int idx = tid + j * 256;
            CP_ASYNC16(bb + 16384 + idx * 16, (const char *)&bhi[c * 2048 + idx * 4]);
            CP_ASYNC16(bb + 24576 + idx * 16, (const char *)&blo[c * 2048 + idx * 4]);
        }
    };

    issue(0, 0); CP_COMMIT();
    issue(1, 1); CP_COMMIT();

    for (int c = 0; c < nchunks; ++c) {
        if (c + 1 < nchunks) { CP_WAIT1(); } else { CP_WAIT0(); }
        __syncthreads();
        if (c + 2 < nchunks) { issue(c + 2, (c + 2) % GPIPE); CP_COMMIT(); }

        const char *stg = smem + (c % GPIPE) * GSTAGE;
        const float *fa = (const float *)stg;
        const uint32_t *fbh = (const uint32_t *)(stg + 16384);
        const uint32_t *fbl = (const uint32_t *)(stg + 24576);
#pragma unroll
        for (int ks = 0; ks < 2; ++ks) {
            uint32_t ah[2][4], al[2][4];
#pragma unroll
            for (int mt = 0; mt < 2; ++mt) {
                int mtg = wm * 2 + mt;
                const float4 *p4 = (const float4 *)&fa[((mtg * 2 + ks) * 32 + lane) * 8];
                float4 u = p4[0], v = p4[1];
                split2_bf16(u.x, u.y, ah[mt][0], al[mt][0]);
                split2_bf16(u.z, u.w, ah[mt][1], al[mt][1]);
                split2_bf16(v.x, v.y, ah[mt][2], al[mt][2]);
                split2_bf16(v.z, v.w, ah[mt][3], al[mt][3]);
            }
#pragma unroll
            for (int nt = 0; nt < 8; ++nt) {
                int ntg = wn * 8 + nt;
                int bidx = ((ntg * 2 + ks) * 32 + lane) * 2;
                uint2 vh = *(const uint2 *)&fbh[bidx];
                uint2 vl = *(const uint2 *)&fbl[bidx];
                uint32_t bh[2] = {vh.x, vh.y};
                uint32_t bl[2] = {vl.x, vl.y};
#pragma unroll
                for (int mt = 0; mt < 2; ++mt) {
                    mma16816(acc[mt][nt], ah[mt], bh);
                    mma16816(acc[mt][nt], ah[mt], bl);
                    mma16816(acc[mt][nt], al[mt], bh);
                }
            }
        }
    }

    // ---- epilogue: y = ds*acc stored as half2 into g_yh ----
    int r = lane >> 2;
#pragma unroll
    for (int mt = 0; mt < 2; ++mt) {
        int rbase = row0 + wm * 32 + mt * 16 + r;
#pragma unroll
        for (int half = 0; half < 2; ++half) {
            int row = rbase + half * 8;
            if (row >= NN) continue;
            float sc = rsqrtf((float)(g_degcnt[row] + 1));
            uint32_t *dst = &g_yh[(size_t)row * 64 + wn * 32 + (lane & 3)];
#pragma unroll
            for (int nt = 0; nt < 8; ++nt) {
                half2 h = __floats2half2_rn(acc[mt][nt][half * 2 + 0] * sc,
                                            acc[mt][nt][half * 2 + 1] * sc);
                dst[nt * 4] = *(uint32_t *)&h;
            }
        }
    }
}

// ------------------------- aggregation: out = relu(ds[d]*(sum_nb y + y[d]) + b) -------------------------
__global__ __launch_bounds__(256) void k_agg(const float *__restrict__ bias, int whichDst,
                                             int fuseScore, const float *__restrict__ Ws) {
    int gw = (blockIdx.x * 256 + threadIdx.x) >> 5;
    int lane = threadIdx.x & 31;
    if (gw >= NN) return;
    float *out = (float *)pickX(whichDst);
    int start = g_rowptr[gw], end = g_rowptr[gw + 1];
    int cu = lane * 2;
    uint2 sv = *(const uint2 *)&g_yh[(size_t)gw * 64 + cu];
    float2 s0 = __half22float2(*(half2 *)&sv.x);
    float2 s1 = __half22float2(*(half2 *)&sv.y);
    float4 acc = make_float4(s0.x, s0.y, s1.x, s1.y);  // self
    int e = start;
    for (; e + 4 <= end; e += 4) {
        int n0 = g_csr[e], n1 = g_csr[e + 1], n2 = g_csr[e + 2], n3 = g_csr[e + 3];
        uint2 v0 = *(const uint2 *)&g_yh[(size_t)n0 * 64 + cu];
        uint2 v1 = *(const uint2 *)&g_yh[(size_t)n1 * 64 + cu];
        uint2 v2 = *(const uint2 *)&g_yh[(size_t)n2 * 64 + cu];
        uint2 v3 = *(const uint2 *)&g_yh[(size_t)n3 * 64 + cu];
        float2 a0 = __half22float2(*(half2 *)&v0.x), b0 = __half22float2(*(half2 *)&v0.y);
        float2 a1 = __half22float2(*(half2 *)&v1.x), b1 = __half22float2(*(half2 *)&v1.y);
        float2 a2 = __half22float2(*(half2 *)&v2.x), b2 = __half22float2(*(half2 *)&v2.y);
        float2 a3 = __half22float2(*(half2 *)&v3.x), b3 = __half22float2(*(half2 *)&v3.y);
        acc.x += (a0.x + a1.x) + (a2.x + a3.x);
        acc.y += (a0.y + a1.y) + (a2.y + a3.y);
        acc.z += (b0.x + b1.x) + (b2.x + b3.x);
        acc.w += (b0.y + b1.y) + (b2.y + b3.y);
    }
    for (; e < end; ++e) {
        int n = g_csr[e];
        uint2 v = *(const uint2 *)&g_yh[(size_t)n * 64 + cu];
        float2 a = __half22float2(*(half2 *)&v.x), b = __half22float2(*(half2 *)&v.y);
        acc.x += a.x; acc.y += a.y; acc.z += b.x; acc.w += b.y;
    }
    float sc = rsqrtf((float)(g_degcnt[gw] + 1));
    int c0 = lane * 4;
    float4 b4 = *(const float4 *)&bias[c0];
    float4 o;
    o.x = fmaxf(fmaf(acc.x, sc, b4.x), 0.f);
    o.y = fmaxf(fmaf(acc.y, sc, b4.y), 0.f);
    o.z = fmaxf(fmaf(acc.z, sc, b4.z), 0.f);
    o.w = fmaxf(fmaf(acc.w, sc, b4.w), 0.f);
    *(float4 *)&out[(size_t)gw * 128 + c0] = o;

    if (fuseScore) {
        float4 w1 = *(const float4 *)&Ws[c0];
        float4 w2 = *(const float4 *)&Ws[128 + c0];
        float4 w3 = *(const float4 *)&Ws[256 + c0];
        float4 x1v = *(const float4 *)&g_x1[(size_t)gw * 128 + c0];
        float4 x2v = *(const float4 *)&g_x2[(size_t)gw * 128 + c0];
        float s = x1v.x * w1.x + x1v.y * w1.y + x1v.z * w1.z + x1v.w * w1.w
                + x2v.x * w2.x + x2v.y * w2.y + x2v.z * w2.z + x2v.w * w2.w
                + o.x * w3.x + o.y * w3.y + o.z * w3.z + o.w * w3.w;
        for (int off = 16; off; off >>= 1) s += __shfl_down_sync(0xFFFFFFFFu, s, off);
        if (lane == 0) g_ysc[gw] = sc * s;
    }
}

// ------------------------- score aggregate (scalar GCN) -------------------------
__global__ __launch_bounds__(256) void k_score_agg(const float *__restrict__ bs) {
    int gw = (blockIdx.x * 256 + threadIdx.x) >> 5;
    int lane = threadIdx.x & 31;
    if (gw >= NN) return;
    int start = g_rowptr[gw], end = g_rowptr[gw + 1];
    float s = 0.f;
    for (int e = start + lane; e < end; e += 32) s += g_ysc[g_csr[e]];
    for (int o = 16; o; o >>= 1) s += __shfl_down_sync(0xFFFFFFFFu, s, o);
    if (lane == 0) {
        float tot = s + g_ysc[gw];
        float sc = fmaf(rsqrtf((float)(g_degcnt[gw] + 1)), tot, bs[0]);
        g_score[gw] = sc;
        g_ukey[gw] = fkey(sc);
    }
}

// ------------------------- persistent-grid radix select + ties (1 kernel) ----------
// 391 blocks x 256 threads, all resident; grid barrier via atomic counter.
__global__ __launch_bounds__(256) void k_radix() {
    __shared__ unsigned sh[256];
    __shared__ unsigned s_pref, s_kp;
    __shared__ unsigned s_phase;
    int t = threadIdx.x;
    int i = blockIdx.x * 256 + t;   // node index (may be >= NN)
    if (t == 0) s_phase = 0u;
    __syncthreads();

    unsigned prefix = 0u, kprime = (unsigned)KKEEP;
    unsigned mykey = (i < NN) ? g_ukey[i] : 0u;

#pragma unroll
    for (int pass = 0; pass < 4; ++pass) {
        sh[t] = 0u;
        __syncthreads();
        if (i < NN) {
            bool m = (pass == 0) || ((mykey >> (32 - 8 * pass)) == prefix);
            if (m) atomicAdd(&sh[(mykey >> (24 - 8 * pass)) & 255u], 1u);
        }
        __syncthreads();
        if (sh[t]) atomicAdd(&g_hist4[pass * 256 + t], sh[t]);
        // ---- grid barrier ----
        __threadfence();
        __syncthreads();
        if (t == 0) {
            unsigned target = s_phase + (unsigned)gridDim.x;
            atomicAdd(&g_barcnt, 1u);
            while (atomicAdd(&g_barcnt, 0u) < target) {}
            s_phase = target;
        }
        __syncthreads();
        // ---- redundant local select (identical in every block) ----
        if (t == 0) {
            unsigned kp = kprime, c = 0;
            int b;
            for (b = 255; b >= 0; --b) {
                unsigned h = g_hist4[pass * 256 + b];
                if (c + h >= kp) break;
                c += h;
            }
            if (b < 0) b = 0;
            s_pref = (prefix << 8) | (unsigned)b;
            s_kp = kp - c;
        }
        __syncthreads();
        prefix = s_pref;
        kprime = s_kp;
    }

    // gate precompute + tie collection
    if (i < NN) {
        g_gate[i] = tanhf(g_score[i]);
        if (mykey == prefix) {
            int p = atomicAdd(&g_nties, 1);
            g_tieidx[p] = i;
        }
    }
    if (blockIdx.x == 0 && t == 0) g_prefix = prefix;
    // ---- grid barrier ----
    __threadfence();
    __syncthreads();
    if (t == 0) {
        unsigned target = s_phase + (unsigned)gridDim.x;
        atomicAdd(&g_barcnt, 1u);
        while (atomicAdd(&g_barcnt, 0u) < target) {}
        s_phase = target;
    }
    __syncthreads();
    // tie resolve (block 0 only; lower index wins)
    if (blockIdx.x == 0) {
        int M = g_nties;
        unsigned R = kprime;
        for (int j = t; j < M; j += 256) {
            int idx = g_tieidx[j];
            unsigned rank = 0;
            for (int l = 0; l < M; ++l) rank += (g_tieidx[l] < idx) ? 1u : 0u;
            if (rank < R) g_tieflag[idx] = 1;
        }
    }
}

// ------------------------- pooling (max + sum over kept nodes, 384 dims) -------------------------
__global__ __launch_bounds__(384) void k_pool() {
    int c = threadIdx.x;
    const float *xa = (c < 128) ? g_x1 : ((c < 256) ? g_x2 : g_x3);
    int cc = c & 127;
    unsigned T = g_prefix;
    float mx = -3.402823466e38f, sm = 0.f;
    for (int i = blockIdx.x; i < NN; i += gridDim.x) {
        unsigned u = g_ukey[i];
        if (u < T) continue;
        if (u == T && !g_tieflag[i]) continue;
        float g = g_gate[i];
        float v = xa[(size_t)i * 128 + cc] * g;
        mx = fmaxf(mx, v);
        sm += v;
    }
    atomicMaxF(&g_gmax[c], mx);
    atomicAdd(&g_gsum[c], sm);
}

// ------------------------- final MLP head (single block) -------------------------
__global__ __launch_bounds__(128) void k_mlp(const float *__restrict__ Wl1, const float *__restrict__ bl1,
                                             const float *__restrict__ Wl2, const float *__restrict__ bl2,
                                             const float *__restrict__ Wl3, const float *__restrict__ bl3,
                                             float *__restrict__ out) {
    __shared__ float h[768], h1[128], h2[64], lg[10];
    int t = threadIdx.x;
    for (int c = t; c < 384; c += 128) {
        h[c] = g_gmax[c];
        h[384 + c] = g_gsum[c] * (1.0f / KKEEP);
    }
    __syncthreads();
    float s = bl1[t];
    for (int i = 0; i < 768; ++i) s = fmaf(h[i], Wl1[i * 128 + t], s);
    h1[t] = fmaxf(s, 0.f);
    __syncthreads();
    if (t < 64) {
        float s2 = bl2[t];
        for (int i = 0; i < 128; ++i) s2 = fmaf(h1[i], Wl2[i * 64 + t], s2);
        h2[t] = fmaxf(s2, 0.f);
    }
    __syncthreads();
    if (t < 10) {
        float s3 = bl3[t];
        for (int i = 0; i < 64; ++i) s3 = fmaf(h2[i], Wl3[i * 10 + t], s3);
        lg[t] = s3;
    }
    __syncthreads();
    if (t == 0) {
        float m = lg[0];
        for (int j = 1; j < 10; ++j) m = fmaxf(m, lg[j]);
        float se = 0.f;
        for (int j = 0; j < 10; ++j) se += expf(lg[j] - m);
        float lse = m + logf(se);
        for (int j = 0; j < 10; ++j) out[j] = lg[j] - lse;
    }
}

// ------------------------- launch -------------------------
extern "C" void kernel_launch(void *const *d_in, const int *in_sizes, int n_in,
                              void *d_out, int out_size) {
    const float *x      = (const float *)d_in[0];
    const int   *ei     = (const int *)d_in[1];   // int32
    const float *W1 = (const float *)d_in[3],  *b1  = (const float *)d_in[4];
    const float *W2 = (const float *)d_in[5],  *b2  = (const float *)d_in[6];
    const float *W3 = (const float *)d_in[7],  *b3  = (const float *)d_in[8];
    const float *Ws = (const float *)d_in[9],  *bs  = (const float *)d_in[10];
    const float *Wl1 = (const float *)d_in[11], *bl1 = (const float *)d_in[12];
    const float *Wl2 = (const float *)d_in[13], *bl2 = (const float *)d_in[14];
    const float *Wl3 = (const float *)d_in[15], *bl3 = (const float *)d_in[16];
    float *out = (float *)d_out;

    const int nblkN = (NN + 255) / 256;
    const int nblkE4 = (EE / 4 + 255) / 256;
    const int nblkW = (NN * 32 + 255) / 256;
    const int nblkT = (NN + 127) / 128;

    static cudaStream_t sCsr = nullptr, sPrep = nullptr;
    static cudaEvent_t evFork = nullptr, evCsr = nullptr, evPrep = nullptr;
    static bool inited = false;
    if (!inited) {
        cudaStreamCreateWithFlags(&sCsr, cudaStreamNonBlocking);
        cudaStreamCreateWithFlags(&sPrep, cudaStreamNonBlocking);
        cudaEventCreateWithFlags(&evFork, cudaEventDisableTiming);
        cudaEventCreateWithFlags(&evCsr, cudaEventDisableTiming);
        cudaEventCreateWithFlags(&evPrep, cudaEventDisableTiming);
        cudaFuncSetAttribute(k_gemm_mma, cudaFuncAttributeMaxDynamicSharedMemorySize, GT_SMEM_BYTES);
        inited = true;
    }

    // ---- origin stream: init, prepB layer0, degree count ----
    k_init<<<nblkN, 256>>>();
    k_prepB<<<(FIN * 64 + 255) / 256, 256>>>(W1, FIN, 0);
    k_count<<<nblkE4, 256>>>(ei);
    cudaEventRecord(evFork, 0);

    // ---- side stream 1: CSR build (overlaps GEMM-1) ----
    cudaStreamWaitEvent(sCsr, evFork, 0);
    k_chunksum<<<NCH, 256, 0, sCsr>>>();
    k_scanchunks<<<1, 1, 0, sCsr>>>();
    k_scanwrite<<<NCH, 1024, 0, sCsr>>>();
    k_scatter<<<nblkE4, 256, 0, sCsr>>>(ei);
    cudaEventRecord(evCsr, sCsr);

    // ---- side stream 2: prepB layers 1,2 ----
    cudaStreamWaitEvent(sPrep, evFork, 0);
    k_prepB<<<(HH * 64 + 255) / 256, 256, 0, sPrep>>>(W2, HH, 1);
    k_prepB<<<(HH * 64 + 255) / 256, 256, 0, sPrep>>>(W3, HH, 2);
    cudaEventRecord(evPrep, sPrep);

    // ---- origin: GCN layer 1 GEMM (concurrent with CSR build) ----
    k_gemm_mma<<<nblkT, 256, GT_SMEM_BYTES>>>(x, 1, 0, FIN, 0);
    cudaStreamWaitEvent(0, evCsr, 0);
    k_agg<<<nblkW, 256>>>(b1, 1, 0, nullptr);
    // layer 2
    cudaStreamWaitEvent(0, evPrep, 0);
    k_gemm_mma<<<nblkT, 256, GT_SMEM_BYTES>>>(nullptr, 0, 1, HH, 1);
    k_agg<<<nblkW, 256>>>(b2, 2, 0, nullptr);
    // layer 3 (+fused score linear)
    k_gemm_mma<<<nblkT, 256, GT_SMEM_BYTES>>>(nullptr, 0, 2, HH, 2);
    k_agg<<<nblkW, 256>>>(b3, 3, 1, Ws);
    // score aggregate
    k_score_agg<<<nblkW, 256>>>(bs);
    // persistent-grid radix select + gate + ties (replaces 10 launches)
    k_radix<<<RBLK, 256>>>();
    // gated max/mean readout over kept nodes
    k_pool<<<512, 384>>>();
    // MLP head + log_softmax
    k_mlp<<<1, 128>>>(Wl1, bl1, Wl2, bl2, Wl3, bl3, out);
}

// round 16
// speedup vs baseline: 1.1139x; 1.0002x over previous
#include <cuda_runtime.h>
#include <cuda_fp16.h>
#include <math.h>
#include <stdint.h>

#define NN 100000
#define EE 1600000
#define FIN 512
#define HH 128
#define KKEEP 50000
#define NCH 98   // ceil(NN/1024)
#define RBLK 391 // ceil(NN/256) persistent blocks for radix megakernel

typedef unsigned long long ull;

// ------------------------- device scratch (globals) -------------------------
__device__ __align__(16) uint32_t g_yh[(size_t)NN * 64];  // y as half2 pairs
__device__ __align__(16) float g_x1[(size_t)NN * HH];
__device__ __align__(16) float g_x2[(size_t)NN * HH];
__device__ __align__(16) float g_x3[(size_t)NN * HH];
__device__ int   g_degcnt[NN];
__device__ int   g_rowptr[NN + 1];
__device__ int   g_fill[NN];
__device__ int   g_csr[EE];
__device__ int   g_chunksum[NCH];
__device__ int   g_chunkoff[NCH];
__device__ float g_ysc[NN];
__device__ float g_score[NN];
__device__ float g_gate[NN];
__device__ unsigned g_ukey[NN];
__device__ unsigned g_hist4[4 * 256];
__device__ unsigned g_barcnt;
__device__ unsigned g_prefix;
__device__ int   g_nties;
__device__ int   g_tieidx[NN];
__device__ int   g_tieflag[NN];
__device__ float g_gmax[384];
__device__ float g_gsum[384];
// pre-split B (W^T) fragments per layer, bf16 hi/lo, chunk-major: [layer][chunk][2048]
__device__ __align__(16) uint32_t g_bhi[3 * 16 * 2048];
__device__ __align__(16) uint32_t g_blo[3 * 16 * 2048];

// ------------------------- small helpers -------------------------
__device__ __forceinline__ unsigned fkey(float f) {
    unsigned u = __float_as_uint(f);
    return (u & 0x80000000u) ? ~u : (u | 0x80000000u);
}
__device__ __forceinline__ void atomicMaxF(float *addr, float val) {
    if (val >= 0.f) atomicMax((int *)addr, __float_as_int(val));
    else            atomicMin((unsigned *)addr, __float_as_uint(val));
}
__device__ __forceinline__ const float *pickX(int w) {
    return w == 1 ? g_x1 : (w == 2 ? g_x2 : g_x3);
}
__device__ __forceinline__ uint32_t pack_bf16x2(float x, float y) {
    uint32_t r;
    asm("cvt.rn.bf16x2.f32 %0, %1, %2;" : "=r"(r) : "f"(y), "f"(x));
    return r;
}
__device__ __forceinline__ float bf16lo_f(uint32_t p) { return __uint_as_float(p << 16); }
__device__ __forceinline__ float bf16hi_f(uint32_t p) { return __uint_as_float(p & 0xFFFF0000u); }
__device__ __forceinline__ void split2_bf16(float x, float y, uint32_t &hi, uint32_t &lo) {
    hi = pack_bf16x2(x, y);
    lo = pack_bf16x2(x - bf16lo_f(hi), y - bf16hi_f(hi));
}
__device__ __forceinline__ void mma16816(float *d, const uint32_t *a, const uint32_t *b) {
    asm volatile("mma.sync.aligned.m16n8k16.row.col.f32.bf16.bf16.f32 "
                 "{%0,%1,%2,%3}, {%4,%5,%6,%7}, {%8,%9}, {%0,%1,%2,%3};"
                 : "+f"(d[0]), "+f"(d[1]), "+f"(d[2]), "+f"(d[3])
                 : "r"(a[0]), "r"(a[1]), "r"(a[2]), "r"(a[3]), "r"(b[0]), "r"(b[1]));
}
#define CP_ASYNC8(dst_u32, src_ptr, szreg) \
    asm volatile("cp.async.ca.shared.global [%0], [%1], 8, %2;" \
                 :: "r"(dst_u32), "l"(src_ptr), "r"(szreg))
#define CP_ASYNC16(dst_u32, src_ptr) \
    asm volatile("cp.async.cg.shared.global [%0], [%1], 16;" \
                 :: "r"(dst_u32), "l"(src_ptr))
#define CP_COMMIT() asm volatile("cp.async.commit_group;" ::: "memory")
#define CP_WAIT1() asm volatile("cp.async.wait_group 1;" ::: "memory")
#define CP_WAIT0() asm volatile("cp.async.wait_group 0;" ::: "memory")

// ------------------------- init -------------------------
__global__ void k_init() {
    int i = blockIdx.x * blockDim.x + threadIdx.x;
    if (i < NN) { g_degcnt[i] = 0; g_fill[i] = 0; g_tieflag[i] = 0; }
    if (i < 384) { g_gmax[i] = -3.402823466e38f; g_gsum[i] = 0.f; }
    if (i < 1024) g_hist4[i] = 0u;
    if (i == 0) { g_barcnt = 0u; g_nties = 0; }
}

// ------------------------- B prep: split W[Kin,128] into fragment-major bf16 hi/lo ----
__global__ void k_prepB(const float *__restrict__ W, int Kin, int layer) {
    int i = blockIdx.x * blockDim.x + threadIdx.x;   // pair index
    if (i >= Kin * 64) return;
    int kp = i >> 7, n = i & 127;
    int k = kp * 2;
    float w0 = W[(size_t)k * 128 + n];
    float w1 = W[(size_t)(k + 1) * 128 + n];
    int c = k >> 5;
    int kk = k & 31;
    int nt = n >> 3, ks = kk >> 4;
    int r = ((kk & 15) >= 8) ? 1 : 0;
    int lane_b = (n & 7) * 4 + ((kk & 7) >> 1);
    int base = layer * 32768 + c * 2048 + ((nt * 2 + ks) * 32 + lane_b) * 2 + r;
    uint32_t h, l;
    split2_bf16(w0, w1, h, l);
    g_bhi[base] = h;
    g_blo[base] = l;
}

// ------------------------- degree / CSR build (edge_index is int32) -------------------------
__global__ void k_count(const int *__restrict__ ei) {
    int e4 = blockIdx.x * blockDim.x + threadIdx.x;
    if (e4 >= EE / 4) return;
    int4 d = *(const int4 *)&ei[EE + e4 * 4];
    atomicAdd(&g_degcnt[d.x], 1);
    atomicAdd(&g_degcnt[d.y], 1);
    atomicAdd(&g_degcnt[d.z], 1);
    atomicAdd(&g_degcnt[d.w], 1);
}
__global__ void k_chunksum() {
    __shared__ int sm[256];
    int t = threadIdx.x, b = blockIdx.x;
    int s = 0;
    for (int j = t; j < 1024; j += 256) {
        int idx = b * 1024 + j;
        if (idx < NN) s += g_degcnt[idx];
    }
    sm[t] = s; __syncthreads();
    for (int o = 128; o; o >>= 1) { if (t < o) sm[t] += sm[t + o]; __syncthreads(); }
    if (t == 0) g_chunksum[b] = sm[0];
}
__global__ void k_scanchunks() {
    int run = 0;
    for (int c = 0; c < NCH; ++c) { g_chunkoff[c] = run; run += g_chunksum[c]; }
    g_rowptr[NN] = EE;
}
__global__ void k_scanwrite() {
    __shared__ int sd[1024];
    int t = threadIdx.x, b = blockIdx.x;
    int idx = b * 1024 + t;
    int v = (idx < NN) ? g_degcnt[idx] : 0;
    int x = v;
    for (int o = 1; o < 1024; o <<= 1) {
        sd[t] = x; __syncthreads();
        if (t >= o) x += sd[t - o];
        __syncthreads();
    }
    if (idx < NN) g_rowptr[idx] = g_chunkoff[b] + x - v;
}
__global__ void k_scatter(const int *__restrict__ ei) {
    int e4 = blockIdx.x * blockDim.x + threadIdx.x;
    if (e4 >= EE / 4) return;
    int4 s = *(const int4 *)&ei[e4 * 4];
    int4 d = *(const int4 *)&ei[EE + e4 * 4];
    g_csr[g_rowptr[d.x] + atomicAdd(&g_fill[d.x], 1)] = s.x;
    g_csr[g_rowptr[d.y] + atomicAdd(&g_fill[d.y], 1)] = s.y;
    g_csr[g_rowptr[d.z] + atomicAdd(&g_fill[d.z], 1)] = s.z;
    g_csr[g_rowptr[d.w] + atomicAdd(&g_fill[d.w], 1)] = s.w;
}

// ------------------------- scale pass: g_yh[row] *= ds[row]  (layer-1 only) ----------
__global__ void k_scale() {
    int i = blockIdx.x * blockDim.x + threadIdx.x;   // uint4 index
    if (i >= NN * 16) return;
    int row = i >> 4;
    float sc = rsqrtf((float)(g_degcnt[row] + 1));
    uint4 v = *(uint4 *)&g_yh[(size_t)i * 4];
    uint32_t r[4] = {v.x, v.y, v.z, v.w};
#pragma unroll
    for (int q = 0; q < 4; ++q) {
        float2 f = __half22float2(*(half2 *)&r[q]);
        half2 h = __floats2half2_rn(f.x * sc, f.y * sc);
        r[q] = *(uint32_t *)&h;
    }
    *(uint4 *)&g_yh[(size_t)i * 4] = make_uint4(r[0], r[1], r[2], r[3]);
}

// ------------------------- GEMM: cp.async pipeline carrying A (f32) + B hi/lo (bf16) ----
// y stored as half2 pairs into g_yh; scaled by ds in-epilogue iff scaleEpi.
#define GPIPE 3
#define GSTAGE 32768
#define GT_SMEM_BYTES (GPIPE * GSTAGE)
__global__ __launch_bounds__(256, 2) void k_gemm_mma(const float *__restrict__ Aext, int useExt,
                                                     int whichSrc, int Kin, int layer,
                                                     int scaleEpi) {
    extern __shared__ char smem[];
    const float *A = useExt ? Aext : pickX(whichSrc);
    uint32_t sbase = (uint32_t)__cvta_generic_to_shared(smem);
    const uint32_t *bhi = g_bhi + layer * 32768;
    const uint32_t *blo = g_blo + layer * 32768;

    int tid = threadIdx.x, wid = tid >> 5, lane = tid & 31;
    int wm = wid & 3, wn = wid >> 2;
    int row0 = blockIdx.x * 128;

    int cp_m[8], cp_dst[8];
    const float *cp_src[8];
#pragma unroll
    for (int it = 0; it < 8; ++it) {
        int i = tid + it * 256;
        int m = i >> 4, p = i & 15;
        int mt = m >> 4, ks = p >> 3;
        int l = (m & 7) * 4 + (p & 3);
        int off = 2 * (((m & 15) >= 8) ? 1 : 0) + 4 * (((p & 7) >= 4) ? 1 : 0);
        int fidx = ((mt * 2 + ks) * 32 + l) * 8 + off;
        cp_m[it] = m;
        cp_dst[it] = fidx * 4;
        cp_src[it] = A + (size_t)(row0 + m) * Kin + p * 2;
    }

    float acc[2][8][4];
#pragma unroll
    for (int mt = 0; mt < 2; ++mt)
#pragma unroll
        for (int nt = 0; nt < 8; ++nt)
#pragma unroll
            for (int q = 0; q < 4; ++q) acc[mt][nt][q] = 0.f;

    int nchunks = Kin >> 5;

    auto issue = [&](int c, int buf) {
        uint32_t bb = sbase + buf * GSTAGE;
#pragma unroll
        for (int it = 0; it < 8; ++it) {
            int valid = (row0 + cp_m[it] < NN) ? 8 : 0;
            CP_ASYNC8(bb + cp_dst[it], cp_src[it] + c * 32, valid);
        }
#pragma unroll
        for (int j = 0; j < 2; ++j) {
            int idx = tid + j * 256;
            CP_ASYNC16(bb + 16384 + idx * 16, (const char *)&bhi[c * 2048 + idx * 4]);
            CP_ASYNC16(bb + 24576 + idx * 16, (const char *)&blo[c * 2048 + idx * 4]);
        }
    };

    issue(0, 0); CP_COMMIT();
    issue(1, 1); CP_COMMIT();

    for (int c = 0; c < nchunks; ++c) {
        if (c + 1 < nchunks) { CP_WAIT1(); } else { CP_WAIT0(); }
        __syncthreads();
        if (c + 2 < nchunks) { issue(c + 2, (c + 2) % GPIPE); CP_COMMIT(); }

        const char *stg = smem + (c % GPIPE) * GSTAGE;
        const float *fa = (const float *)stg;
        const uint32_t *fbh = (const uint32_t *)(stg + 16384);
        const uint32_t *fbl = (const uint32_t *)(stg + 24576);
#pragma unroll
        for (int ks = 0; ks < 2; ++ks) {
            uint32_t ah[2][4], al[2][4];
#pragma unroll
            for (int mt = 0; mt < 2; ++mt) {
                int mtg = wm * 2 + mt;
                const float4 *p4 = (const float4 *)&fa[((mtg * 2 + ks) * 32 + lane) * 8];
                float4 u = p4[0], v = p4[1];
                split2_bf16(u.x, u.y, ah[mt][0], al[mt][0]);
                split2_bf16(u.z, u.w, ah[mt][1], al[mt][1]);
                split2_bf16(v.x, v.y, ah[mt][2], al[mt][2]);
                split2_bf16(v.z, v.w, ah[mt][3], al[mt][3]);
            }
#pragma unroll
            for (int nt = 0; nt < 8; ++nt) {
                int ntg = wn * 8 + nt;
                int bidx = ((ntg * 2 + ks) * 32 + lane) * 2;
                uint2 vh = *(const uint2 *)&fbh[bidx];
                uint2 vl = *(const uint2 *)&fbl[bidx];
                uint32_t bh[2] = {vh.x, vh.y};
                uint32_t bl[2] = {vl.x, vl.y};
#pragma unroll
                for (int mt = 0; mt < 2; ++mt) {
                    mma16816(acc[mt][nt], ah[mt], bh);
                    mma16816(acc[mt][nt], ah[mt], bl);
                    mma16816(acc[mt][nt], al[mt], bh);
                }
            }
        }
    }

    // ---- epilogue: y (optionally ds-scaled) stored as half2 into g_yh ----
    int r = lane >> 2;
#pragma unroll
    for (int mt = 0; mt < 2; ++mt) {
        int rbase = row0 + wm * 32 + mt * 16 + r;
#pragma unroll
        for (int half = 0; half < 2; ++half) {
            int row = rbase + half * 8;
            if (row >= NN) continue;
            float sc = 1.f;
            if (scaleEpi) sc = rsqrtf((float)(g_degcnt[row] + 1));
            uint32_t *dst = &g_yh[(size_t)row * 64 + wn * 32 + (lane & 3)];
#pragma unroll
            for (int nt = 0; nt < 8; ++nt) {
                half2 h = __floats2half2_rn(acc[mt][nt][half * 2 + 0] * sc,
                                            acc[mt][nt][half * 2 + 1] * sc);
                dst[nt * 4] = *(uint32_t *)&h;
            }
        }
    }
}

// ------------------------- aggregation: out = relu(ds[d]*(sum_nb y + y[d]) + b) -------------------------
__global__ __launch_bounds__(256) void k_agg(const float *__restrict__ bias, int whichDst,
                                             int fuseScore, const float *__restrict__ Ws) {
    int gw = (blockIdx.x * 256 + threadIdx.x) >> 5;
    int lane = threadIdx.x & 31;
    if (gw >= NN) return;
    float *out = (float *)pickX(whichDst);
    int start = g_rowptr[gw], end = g_rowptr[gw + 1];
    int cu = lane * 2;
    uint2 sv = *(const uint2 *)&g_yh[(size_t)gw * 64 + cu];
    float2 s0 = __half22float2(*(half2 *)&sv.x);
    float2 s1 = __half22float2(*(half2 *)&sv.y);
    float4 acc = make_float4(s0.x, s0.y, s1.x, s1.y);  // self
    int e = start;
    for (; e + 4 <= end; e += 4) {
        int n0 = g_csr[e], n1 = g_csr[e + 1], n2 = g_csr[e + 2], n3 = g_csr[e + 3];
        uint2 v0 = *(const uint2 *)&g_yh[(size_t)n0 * 64 + cu];
        uint2 v1 = *(const uint2 *)&g_yh[(size_t)n1 * 64 + cu];
        uint2 v2 = *(const uint2 *)&g_yh[(size_t)n2 * 64 + cu];
        uint2 v3 = *(const uint2 *)&g_yh[(size_t)n3 * 64 + cu];
        float2 a0 = __half22float2(*(half2 *)&v0.x), b0 = __half22float2(*(half2 *)&v0.y);
        float2 a1 = __half22float2(*(half2 *)&v1.x), b1 = __half22float2(*(half2 *)&v1.y);
        float2 a2 = __half22float2(*(half2 *)&v2.x), b2 = __half22float2(*(half2 *)&v2.y);
        float2 a3 = __half22float2(*(half2 *)&v3.x), b3 = __half22float2(*(half2 *)&v3.y);
        acc.x += (a0.x + a1.x) + (a2.x + a3.x);
        acc.y += (a0.y + a1.y) + (a2.y + a3.y);
        acc.z += (b0.x + b1.x) + (b2.x + b3.x);
        acc.w += (b0.y + b1.y) + (b2.y + b3.y);
    }
    for (; e < end; ++e) {
        int n = g_csr[e];
        uint2 v = *(const uint2 *)&g_yh[(size_t)n * 64 + cu];
        float2 a = __half22float2(*(half2 *)&v.x), b = __half22float2(*(half2 *)&v.y);
        acc.x += a.x; acc.y += a.y; acc.z += b.x; acc.w += b.y;
    }
    float sc = rsqrtf((float)(g_degcnt[gw] + 1));
    int c0 = lane * 4;
    float4 b4 = *(const float4 *)&bias[c0];
    float4 o;
    o.x = fmaxf(fmaf(acc.x, sc, b4.x), 0.f);
    o.y = fmaxf(fmaf(acc.y, sc, b4.y), 0.f);
    o.z = fmaxf(fmaf(acc.z, sc, b4.z), 0.f);
    o.w = fmaxf(fmaf(acc.w, sc, b4.w), 0.f);
    *(float4 *)&out[(size_t)gw * 128 + c0] = o;

    if (fuseScore) {
        float4 w1 = *(const float4 *)&Ws[c0];
        float4 w2 = *(const float4 *)&Ws[128 + c0];
        float4 w3 = *(const float4 *)&Ws[256 + c0];
        float4 x1v = *(const float4 *)&g_x1[(size_t)gw * 128 + c0];
        float4 x2v = *(const float4 *)&g_x2[(size_t)gw * 128 + c0];
        float s = x1v.x * w1.x + x1v.y * w1.y + x1v.z * w1.z + x1v.w * w1.w
                + x2v.x * w2.x + x2v.y * w2.y + x2v.z * w2.z + x2v.w * w2.w
                + o.x * w3.x + o.y * w3.y + o.z * w3.z + o.w * w3.w;
        for (int off = 16; off; off >>= 1) s += __shfl_down_sync(0xFFFFFFFFu, s, off);
        if (lane == 0) g_ysc[gw] = sc * s;
    }
}

// ------------------------- score aggregate (scalar GCN) -------------------------
__global__ __launch_bounds__(256) void k_score_agg(const float *__restrict__ bs) {
    int gw = (blockIdx.x * 256 + threadIdx.x) >> 5;
    int lane = threadIdx.x & 31;
    if (gw >= NN) return;
    int start = g_rowptr[gw], end = g_rowptr[gw + 1];
    float s = 0.f;
    for (int e = start + lane; e < end; e += 32) s += g_ysc[g_csr[e]];
    for (int o = 16; o; o >>= 1) s += __shfl_down_sync(0xFFFFFFFFu, s, o);
    if (lane == 0) {
        float tot = s + g_ysc[gw];
        float sc = fmaf(rsqrtf((float)(g_degcnt[gw] + 1)), tot, bs[0]);
        g_score[gw] = sc;
        g_ukey[gw] = fkey(sc);
    }
}

// ------------------------- persistent-grid radix select + ties (1 kernel) ----------
__global__ __launch_bounds__(256) void k_radix() {
    __shared__ unsigned sh[256];
    __shared__ unsigned s_pref, s_kp;
    __shared__ unsigned s_phase;
    int t = threadIdx.x;
    int i = blockIdx.x * 256 + t;
    if (t == 0) s_phase = 0u;
    __syncthreads();

    unsigned prefix = 0u, kprime = (unsigned)KKEEP;
    unsigned mykey = (i < NN) ? g_ukey[i] : 0u;

#pragma unroll
    for (int pass = 0; pass < 4; ++pass) {
        sh[t] = 0u;
        __syncthreads();
        if (i < NN) {
            bool m = (pass == 0) || ((mykey >> (32 - 8 * pass)) == prefix);
            if (m) atomicAdd(&sh[(mykey >> (24 - 8 * pass)) & 255u], 1u);
        }
        __syncthreads();
        if (sh[t]) atomicAdd(&g_hist4[pass * 256 + t], sh[t]);
        __threadfence();
        __syncthreads();
        if (t == 0) {
            unsigned target = s_phase + (unsigned)gridDim.x;
            atomicAdd(&g_barcnt, 1u);
            while (atomicAdd(&g_barcnt, 0u) < target) {}
            s_phase = target;
        }
        __syncthreads();
        if (t == 0) {
            unsigned kp = kprime, c = 0;
            int b;
            for (b = 255; b >= 0; --b) {
                unsigned h = g_hist4[pass * 256 + b];
                if (c + h >= kp) break;
                c += h;
            }
            if (b < 0) b = 0;
            s_pref = (prefix << 8) | (unsigned)b;
            s_kp = kp - c;
        }
        __syncthreads();
        prefix = s_pref;
        kprime = s_kp;
    }

    if (i < NN) {
        g_gate[i] = tanhf(g_score[i]);
        if (mykey == prefix) {
            int p = atomicAdd(&g_nties, 1);
            g_tieidx[p] = i;
        }
    }
    if (blockIdx.x == 0 && t == 0) g_prefix = prefix;
    __threadfence();
    __syncthreads();
    if (t == 0) {
        unsigned target = s_phase + (unsigned)gridDim.x;
        atomicAdd(&g_barcnt, 1u);
        while (atomicAdd(&g_barcnt, 0u) < target) {}
        s_phase = target;
    }
    __syncthreads();
    if (blockIdx.x == 0) {
        int M = g_nties;
        unsigned R = kprime;
        for (int j = t; j < M; j += 256) {
            int idx = g_tieidx[j];
            unsigned rank = 0;
            for (int l = 0; l < M; ++l) rank += (g_tieidx[l] < idx) ? 1u : 0u;
            if (rank < R) g_tieflag[idx] = 1;
        }
    }
}

// ------------------------- pooling (max + sum over kept nodes, 384 dims) -------------------------
__global__ __launch_bounds__(384) void k_pool() {
    int c = threadIdx.x;
    const float *xa = (c < 128) ? g_x1 : ((c < 256) ? g_x2 : g_x3);
    int cc = c & 127;
    unsigned T = g_prefix;
    float mx = -3.402823466e38f, sm = 0.f;
    for (int i = blockIdx.x; i < NN; i += gridDim.x) {
        unsigned u = g_ukey[i];
        if (u < T) continue;
        if (u == T && !g_tieflag[i]) continue;
        float g = g_gate[i];
        float v = xa[(size_t)i * 128 + cc] * g;
        mx = fmaxf(mx, v);
        sm += v;
    }
    atomicMaxF(&g_gmax[c], mx);
    atomicAdd(&g_gsum[c], sm);
}

// ------------------------- final MLP head (single block) -------------------------
__global__ __launch_bounds__(128) void k_mlp(const float *__restrict__ Wl1, const float *__restrict__ bl1,
                                             const float *__restrict__ Wl2, const float *__restrict__ bl2,
                                             const float *__restrict__ Wl3, const float *__restrict__ bl3,
                                             float *__restrict__ out) {
    __shared__ float h[768], h1[128], h2[64], lg[10];
    int t = threadIdx.x;
    for (int c = t; c < 384; c += 128) {
        h[c] = g_gmax[c];
        h[384 + c] = g_gsum[c] * (1.0f / KKEEP);
    }
    __syncthreads();
    float s = bl1[t];
    for (int i = 0; i < 768; ++i) s = fmaf(h[i], Wl1[i * 128 + t], s);
    h1[t] = fmaxf(s, 0.f);
    __syncthreads();
    if (t < 64) {
        float s2 = bl2[t];
        for (int i = 0; i < 128; ++i) s2 = fmaf(h1[i], Wl2[i * 64 + t], s2);
        h2[t] = fmaxf(s2, 0.f);
    }
    __syncthreads();
    if (t < 10) {
        float s3 = bl3[t];
        for (int i = 0; i < 64; ++i) s3 = fmaf(h2[i], Wl3[i * 10 + t], s3);
        lg[t] = s3;
    }
    __syncthreads();
    if (t == 0) {
        float m = lg[0];
        for (int j = 1; j < 10; ++j) m = fmaxf(m, lg[j]);
        float se = 0.f;
        for (int j = 0; j < 10; ++j) se += expf(lg[j] - m);
        float lse = m + logf(se);
        for (int j = 0; j < 10; ++j) out[j] = lg[j] - lse;
    }
}

// ------------------------- launch -------------------------
extern "C" void kernel_launch(void *const *d_in, const int *in_sizes, int n_in,
                              void *d_out, int out_size) {
    const float *x      = (const float *)d_in[0];
    const int   *ei     = (const int *)d_in[1];   // int32
    const float *W1 = (const float *)d_in[3],  *b1  = (const float *)d_in[4];
    const float *W2 = (const float *)d_in[5],  *b2  = (const float *)d_in[6];
    const float *W3 = (const float *)d_in[7],  *b3  = (const float *)d_in[8];
    const float *Ws = (const float *)d_in[9],  *bs  = (const float *)d_in[10];
    const float *Wl1 = (const float *)d_in[11], *bl1 = (const float *)d_in[12];
    const float *Wl2 = (const float *)d_in[13], *bl2 = (const float *)d_in[14];
    const float *Wl3 = (const float *)d_in[15], *bl3 = (const float *)d_in[16];
    float *out = (float *)d_out;

    const int nblkN = (NN + 255) / 256;
    const int nblkE4 = (EE / 4 + 255) / 256;
    const int nblkW = (NN * 32 + 255) / 256;
    const int nblkT = (NN + 127) / 128;
    const int nblkS = (NN * 16 + 255) / 256;

    static cudaStream_t sCsr = nullptr, sPrep = nullptr;
    static cudaEvent_t evFork = nullptr, evCsr = nullptr, evPrep = nullptr;
    static bool inited = false;
    if (!inited) {
        cudaStreamCreateWithFlags(&sCsr, cudaStreamNonBlocking);
        cudaStreamCreateWithFlags(&sPrep, cudaStreamNonBlocking);
        cudaEventCreateWithFlags(&evFork, cudaEventDisableTiming);
        cudaEventCreateWithFlags(&evCsr, cudaEventDisableTiming);
        cudaEventCreateWithFlags(&evPrep, cudaEventDisableTiming);
        cudaFuncSetAttribute(k_gemm_mma, cudaFuncAttributeMaxDynamicSharedMemorySize, GT_SMEM_BYTES);
        inited = true;
    }

    // ---- origin: init + prepB1 only (GEMM-1 has no degcnt dep now) ----
    k_init<<<nblkN, 256>>>();
    cudaEventRecord(evFork, 0);
    k_prepB<<<(FIN * 64 + 255) / 256, 256>>>(W1, FIN, 0);

    // ---- side stream 1: full edge pipeline (count + CSR), overlaps GEMM-1 ----
    cudaStreamWaitEvent(sCsr, evFork, 0);
    k_count<<<nblkE4, 256, 0, sCsr>>>(ei);
    k_chunksum<<<NCH, 256, 0, sCsr>>>();
    k_scanchunks<<<1, 1, 0, sCsr>>>();
    k_scanwrite<<<NCH, 1024, 0, sCsr>>>();
    k_scatter<<<nblkE4, 256, 0, sCsr>>>(ei);
    cudaEventRecord(evCsr, sCsr);

    // ---- side stream 2: prepB layers 1,2 ----
    cudaStreamWaitEvent(sPrep, evFork, 0);
    k_prepB<<<(HH * 64 + 255) / 256, 256, 0, sPrep>>>(W2, HH, 1);
    k_prepB<<<(HH * 64 + 255) / 256, 256, 0, sPrep>>>(W3, HH, 2);
    cudaEventRecord(evPrep, sPrep);

    // ---- origin: GCN layer 1 GEMM (unscaled; fully concurrent with edge pipeline) ----
    k_gemm_mma<<<nblkT, 256, GT_SMEM_BYTES>>>(x, 1, 0, FIN, 0, 0);
    cudaStreamWaitEvent(0, evCsr, 0);
    k_scale<<<nblkS, 256>>>();              // apply ds after count completes
    k_agg<<<nblkW, 256>>>(b1, 1, 0, nullptr);
    // layer 2 (epilogue-scaled)
    cudaStreamWaitEvent(0, evPrep, 0);
    k_gemm_mma<<<nblkT, 256, GT_SMEM_BYTES>>>(nullptr, 0, 1, HH, 1, 1);
    k_agg<<<nblkW, 256>>>(b2, 2, 0, nullptr);
    // layer 3 (+fused score linear)
    k_gemm_mma<<<nblkT, 256, GT_SMEM_BYTES>>>(nullptr, 0, 2, HH, 2, 1);
    k_agg<<<nblkW, 256>>>(b3, 3, 1, Ws);
    // score aggregate
    k_score_agg<<<nblkW, 256>>>(bs);
    // persistent-grid radix select + gate + ties
    k_radix<<<RBLK, 256>>>();
    // gated max/mean readout over kept nodes
    k_pool<<<512, 384>>>();
    // MLP head + log_softmax
    k_mlp<<<1, 128>>>(Wl1, bl1, Wl2, bl2, Wl3, bl3, out);
}

// round 17
// speedup vs baseline: 1.2310x; 1.1051x over previous
#include <cuda_runtime.h>
#include <cuda_fp16.h>
#include <math.h>
#include <stdint.h>

#define NN 100000
#define EE 1600000
#define FIN 512
#define HH 128
#define KKEEP 50000
#define NCH 98   // ceil(NN/1024)
#define RBLK 391 // ceil(NN/256) persistent blocks for radix megakernel

typedef unsigned long long ull;

// ------------------------- device scratch (globals) -------------------------
__device__ __align__(16) uint32_t g_yh[(size_t)NN * 64];  // y as half2 pairs
__device__ __align__(16) float g_x1[(size_t)NN * HH];
__device__ __align__(16) float g_x2[(size_t)NN * HH];
__device__ __align__(16) float g_x3[(size_t)NN * HH];
__device__ int   g_degcnt[NN];
__device__ int   g_rowptr[NN + 1];
__device__ int   g_fill[NN];
__device__ int   g_csr[EE];
__device__ int   g_chunksum[NCH];
__device__ int   g_chunkoff[NCH];
__device__ float g_ysc[NN];
__device__ float g_score[NN];
__device__ float g_gate[NN];
__device__ unsigned g_ukey[NN];
__device__ unsigned g_hist4[4 * 256];
__device__ unsigned g_barcnt;
__device__ unsigned g_prefix;
__device__ int   g_nties;
__device__ int   g_tieidx[NN];
__device__ int   g_tieflag[NN];
__device__ float g_gmax[384];
__device__ float g_gsum[384];
// pre-converted B (W^T) fragments per layer, fp16, chunk-major: [layer][chunk][2048]
__device__ __align__(16) uint32_t g_bh[3 * 16 * 2048];

// ------------------------- small helpers -------------------------
__device__ __forceinline__ unsigned fkey(float f) {
    unsigned u = __float_as_uint(f);
    return (u & 0x80000000u) ? ~u : (u | 0x80000000u);
}
__device__ __forceinline__ void atomicMaxF(float *addr, float val) {
    if (val >= 0.f) atomicMax((int *)addr, __float_as_int(val));
    else            atomicMin((unsigned *)addr, __float_as_uint(val));
}
__device__ __forceinline__ const float *pickX(int w) {
    return w == 1 ? g_x1 : (w == 2 ? g_x2 : g_x3);
}
__device__ __forceinline__ uint32_t pack_h2(float x, float y) {
    half2 h = __floats2half2_rn(x, y);
    return *(uint32_t *)&h;
}
__device__ __forceinline__ void mma16816f16(float *d, const uint32_t *a, const uint32_t *b) {
    asm volatile("mma.sync.aligned.m16n8k16.row.col.f32.f16.f16.f32 "
                 "{%0,%1,%2,%3}, {%4,%5,%6,%7}, {%8,%9}, {%0,%1,%2,%3};"
                 : "+f"(d[0]), "+f"(d[1]), "+f"(d[2]), "+f"(d[3])
                 : "r"(a[0]), "r"(a[1]), "r"(a[2]), "r"(a[3]), "r"(b[0]), "r"(b[1]));
}
#define CP_ASYNC8(dst_u32, src_ptr, szreg) \
    asm volatile("cp.async.ca.shared.global [%0], [%1], 8, %2;" \
                 :: "r"(dst_u32), "l"(src_ptr), "r"(szreg))
#define CP_ASYNC16(dst_u32, src_ptr) \
    asm volatile("cp.async.cg.shared.global [%0], [%1], 16;" \
                 :: "r"(dst_u32), "l"(src_ptr))
#define CP_COMMIT() asm volatile("cp.async.commit_group;" ::: "memory")
#define CP_WAIT1() asm volatile("cp.async.wait_group 1;" ::: "memory")
#define CP_WAIT0() asm volatile("cp.async.wait_group 0;" ::: "memory")

// ------------------------- init -------------------------
__global__ void k_init() {
    int i = blockIdx.x * blockDim.x + threadIdx.x;
    if (i < NN) { g_degcnt[i] = 0; g_fill[i] = 0; g_tieflag[i] = 0; }
    if (i < 384) { g_gmax[i] = -3.402823466e38f; g_gsum[i] = 0.f; }
    if (i < 1024) g_hist4[i] = 0u;
    if (i == 0) { g_barcnt = 0u; g_nties = 0; }
}

// ------------------------- B prep: W[Kin,128] -> fragment-major fp16 ----
__global__ void k_prepB(const float *__restrict__ W, int Kin, int layer) {
    int i = blockIdx.x * blockDim.x + threadIdx.x;   // pair index
    if (i >= Kin * 64) return;
    int kp = i >> 7, n = i & 127;
    int k = kp * 2;
    float w0 = W[(size_t)k * 128 + n];
    float w1 = W[(size_t)(k + 1) * 128 + n];
    int c = k >> 5;
    int kk = k & 31;
    int nt = n >> 3, ks = kk >> 4;
    int r = ((kk & 15) >= 8) ? 1 : 0;
    int lane_b = (n & 7) * 4 + ((kk & 7) >> 1);
    int base = layer * 32768 + c * 2048 + ((nt * 2 + ks) * 32 + lane_b) * 2 + r;
    g_bh[base] = pack_h2(w0, w1);
}

// ------------------------- degree / CSR build (edge_index is int32) -------------------------
__global__ void k_count(const int *__restrict__ ei) {
    int e4 = blockIdx.x * blockDim.x + threadIdx.x;
    if (e4 >= EE / 4) return;
    int4 d = *(const int4 *)&ei[EE + e4 * 4];
    atomicAdd(&g_degcnt[d.x], 1);
    atomicAdd(&g_degcnt[d.y], 1);
    atomicAdd(&g_degcnt[d.z], 1);
    atomicAdd(&g_degcnt[d.w], 1);
}
__global__ void k_chunksum() {
    __shared__ int sm[256];
    int t = threadIdx.x, b = blockIdx.x;
    int s = 0;
    for (int j = t; j < 1024; j += 256) {
        int idx = b * 1024 + j;
        if (idx < NN) s += g_degcnt[idx];
    }
    sm[t] = s; __syncthreads();
    for (int o = 128; o; o >>= 1) { if (t < o) sm[t] += sm[t + o]; __syncthreads(); }
    if (t == 0) g_chunksum[b] = sm[0];
}
__global__ void k_scanchunks() {
    int run = 0;
    for (int c = 0; c < NCH; ++c) { g_chunkoff[c] = run; run += g_chunksum[c]; }
    g_rowptr[NN] = EE;
}
__global__ void k_scanwrite() {
    __shared__ int sd[1024];
    int t = threadIdx.x, b = blockIdx.x;
    int idx = b * 1024 + t;
    int v = (idx < NN) ? g_degcnt[idx] : 0;
    int x = v;
    for (int o = 1; o < 1024; o <<= 1) {
        sd[t] = x; __syncthreads();
        if (t >= o) x += sd[t - o];
        __syncthreads();
    }
    if (idx < NN) g_rowptr[idx] = g_chunkoff[b] + x - v;
}
__global__ void k_scatter(const int *__restrict__ ei) {
    int e4 = blockIdx.x * blockDim.x + threadIdx.x;
    if (e4 >= EE / 4) return;
    int4 s = *(const int4 *)&ei[e4 * 4];
    int4 d = *(const int4 *)&ei[EE + e4 * 4];
    g_csr[g_rowptr[d.x] + atomicAdd(&g_fill[d.x], 1)] = s.x;
    g_csr[g_rowptr[d.y] + atomicAdd(&g_fill[d.y], 1)] = s.y;
    g_csr[g_rowptr[d.z] + atomicAdd(&g_fill[d.z], 1)] = s.z;
    g_csr[g_rowptr[d.w] + atomicAdd(&g_fill[d.w], 1)] = s.w;
}

// ------------------------- scale pass: g_yh[row] *= ds[row]  (layer-1 only) ----------
__global__ void k_scale() {
    int i = blockIdx.x * blockDim.x + threadIdx.x;   // uint4 index
    if (i >= NN * 16) return;
    int row = i >> 4;
    float sc = rsqrtf((float)(g_degcnt[row] + 1));
    uint4 v = *(uint4 *)&g_yh[(size_t)i * 4];
    uint32_t r[4] = {v.x, v.y, v.z, v.w};
#pragma unroll
    for (int q = 0; q < 4; ++q) {
        float2 f = __half22float2(*(half2 *)&r[q]);
        half2 h = __floats2half2_rn(f.x * sc, f.y * sc);
        r[q] = *(uint32_t *)&h;
    }
    *(uint4 *)&g_yh[(size_t)i * 4] = make_uint4(r[0], r[1], r[2], r[3]);
}

// ------------------------- GEMM: cp.async pipeline, fp16 MMA (single-term) ----------
// Stage (24KB): [A f32 frag 16KB][B fp16 8KB], 3 stages.
#define GPIPE 3
#define GSTAGE 24576
#define GT_SMEM_BYTES (GPIPE * GSTAGE)
__global__ __launch_bounds__(256, 2) void k_gemm_mma(const float *__restrict__ Aext, int useExt,
                                                     int whichSrc, int Kin, int layer,
                                                     int scaleEpi) {
    extern __shared__ char smem[];
    const float *A = useExt ? Aext : pickX(whichSrc);
    uint32_t sbase = (uint32_t)__cvta_generic_to_shared(smem);
    const uint32_t *bh = g_bh + layer * 32768;

    int tid = threadIdx.x, wid = tid >> 5, lane = tid & 31;
    int wm = wid & 3, wn = wid >> 2;
    int row0 = blockIdx.x * 128;

    int cp_m[8], cp_dst[8];
    const float *cp_src[8];
#pragma unroll
    for (int it = 0; it < 8; ++it) {
        int i = tid + it * 256;
        int m = i >> 4, p = i & 15;
        int mt = m >> 4, ks = p >> 3;
        int l = (m & 7) * 4 + (p & 3);
        int off = 2 * (((m & 15) >= 8) ? 1 : 0) + 4 * (((p & 7) >= 4) ? 1 : 0);
        int fidx = ((mt * 2 + ks) * 32 + l) * 8 + off;
        cp_m[it] = m;
        cp_dst[it] = fidx * 4;
        cp_src[it] = A + (size_t)(row0 + m) * Kin + p * 2;
    }

    float acc[2][8][4];
#pragma unroll
    for (int mt = 0; mt < 2; ++mt)
#pragma unroll
        for (int nt = 0; nt < 8; ++nt)
#pragma unroll
            for (int q = 0; q < 4; ++q) acc[mt][nt][q] = 0.f;

    int nchunks = Kin >> 5;

    auto issue = [&](int c, int buf) {
        uint32_t bb = sbase + buf * GSTAGE;
#pragma unroll
        for (int it = 0; it < 8; ++it) {
            int valid = (row0 + cp_m[it] < NN) ? 8 : 0;
            CP_ASYNC8(bb + cp_dst[it], cp_src[it] + c * 32, valid);
        }
        // B: 2048 u32 = 512 x 16B; 2 per thread
#pragma unroll
        for (int j = 0; j < 2; ++j) {
            int idx = tid + j * 256;
            CP_ASYNC16(bb + 16384 + idx * 16, (const char *)&bh[c * 2048 + idx * 4]);
        }
    };

    issue(0, 0); CP_COMMIT();
    issue(1, 1); CP_COMMIT();

    for (int c = 0; c < nchunks; ++c) {
        if (c + 1 < nchunks) { CP_WAIT1(); } else { CP_WAIT0(); }
        __syncthreads();
        if (c + 2 < nchunks) { issue(c + 2, (c + 2) % GPIPE); CP_COMMIT(); }

        const char *stg = smem + (c % GPIPE) * GSTAGE;
        const float *fa = (const float *)stg;
        const uint32_t *fbh = (const uint32_t *)(stg + 16384);
#pragma unroll
        for (int ks = 0; ks < 2; ++ks) {
            uint32_t ah[2][4];
#pragma unroll
            for (int mt = 0; mt < 2; ++mt) {
                int mtg = wm * 2 + mt;
                const float4 *p4 = (const float4 *)&fa[((mtg * 2 + ks) * 32 + lane) * 8];
                float4 u = p4[0], v = p4[1];
                ah[mt][0] = pack_h2(u.x, u.y);
                ah[mt][1] = pack_h2(u.z, u.w);
                ah[mt][2] = pack_h2(v.x, v.y);
                ah[mt][3] = pack_h2(v.z, v.w);
            }
#pragma unroll
            for (int nt = 0; nt < 8; ++nt) {
                int ntg = wn * 8 + nt;
                int bidx = ((ntg * 2 + ks) * 32 + lane) * 2;
                uint2 vh = *(const uint2 *)&fbh[bidx];
                uint32_t bfr[2] = {vh.x, vh.y};
#pragma unroll
                for (int mt = 0; mt < 2; ++mt)
                    mma16816f16(acc[mt][nt], ah[mt], bfr);
            }
        }
    }

    // ---- epilogue: y (optionally ds-scaled) stored as half2 into g_yh ----
    int r = lane >> 2;
#pragma unroll
    for (int mt = 0; mt < 2; ++mt) {
        int rbase = row0 + wm * 32 + mt * 16 + r;
#pragma unroll
        for (int half = 0; half < 2; ++half) {
            int row = rbase + half * 8;
            if (row >= NN) continue;
            float sc = 1.f;
            if (scaleEpi) sc = rsqrtf((float)(g_degcnt[row] + 1));
            uint32_t *dst = &g_yh[(size_t)row * 64 + wn * 32 + (lane & 3)];
#pragma unroll
            for (int nt = 0; nt < 8; ++nt) {
                half2 h = __floats2half2_rn(acc[mt][nt][half * 2 + 0] * sc,
                                            acc[mt][nt][half * 2 + 1] * sc);
                dst[nt * 4] = *(uint32_t *)&h;
            }
        }
    }
}

// ------------------------- aggregation: out = relu(ds[d]*(sum_nb y + y[d]) + b) -------------------------
__global__ __launch_bounds__(256) void k_agg(const float *__restrict__ bias, int whichDst,
                                             int fuseScore, const float *__restrict__ Ws) {
    int gw = (blockIdx.x * 256 + threadIdx.x) >> 5;
    int lane = threadIdx.x & 31;
    if (gw >= NN) return;
    float *out = (float *)pickX(whichDst);
    int start = g_rowptr[gw], end = g_rowptr[gw + 1];
    int cu = lane * 2;
    uint2 sv = *(const uint2 *)&g_yh[(size_t)gw * 64 + cu];
    float2 s0 = __half22float2(*(half2 *)&sv.x);
    float2 s1 = __half22float2(*(half2 *)&sv.y);
    float4 acc = make_float4(s0.x, s0.y, s1.x, s1.y);  // self
    int e = start;
    for (; e + 4 <= end; e += 4) {
        int n0 = g_csr[e], n1 = g_csr[e + 1], n2 = g_csr[e + 2], n3 = g_csr[e + 3];
        uint2 v0 = *(const uint2 *)&g_yh[(size_t)n0 * 64 + cu];
        uint2 v1 = *(const uint2 *)&g_yh[(size_t)n1 * 64 + cu];
        uint2 v2 = *(const uint2 *)&g_yh[(size_t)n2 * 64 + cu];
        uint2 v3 = *(const uint2 *)&g_yh[(size_t)n3 * 64 + cu];
        float2 a0 = __half22float2(*(half2 *)&v0.x), b0 = __half22float2(*(half2 *)&v0.y);
        float2 a1 = __half22float2(*(half2 *)&v1.x), b1 = __half22float2(*(half2 *)&v1.y);
        float2 a2 = __half22float2(*(half2 *)&v2.x), b2 = __half22float2(*(half2 *)&v2.y);
        float2 a3 = __half22float2(*(half2 *)&v3.x), b3 = __half22float2(*(half2 *)&v3.y);
        acc.x += (a0.x + a1.x) + (a2.x + a3.x);
        acc.y += (a0.y + a1.y) + (a2.y + a3.y);
        acc.z += (b0.x + b1.x) + (b2.x + b3.x);
        acc.w += (b0.y + b1.y) + (b2.y + b3.y);
    }
    for (; e < end; ++e) {
        int n = g_csr[e];
        uint2 v = *(const uint2 *)&g_yh[(size_t)n * 64 + cu];
        float2 a = __half22float2(*(half2 *)&v.x), b = __half22float2(*(half2 *)&v.y);
        acc.x += a.x; acc.y += a.y; acc.z += b.x; acc.w += b.y;
    }
    float sc = rsqrtf((float)(g_degcnt[gw] + 1));
    int c0 = lane * 4;
    float4 b4 = *(const float4 *)&bias[c0];
    float4 o;
    o.x = fmaxf(fmaf(acc.x, sc, b4.x), 0.f);
    o.y = fmaxf(fmaf(acc.y, sc, b4.y), 0.f);
    o.z = fmaxf(fmaf(acc.z, sc, b4.z), 0.f);
    o.w = fmaxf(fmaf(acc.w, sc, b4.w), 0.f);
    *(float4 *)&out[(size_t)gw * 128 + c0] = o;

    if (fuseScore) {
        float4 w1 = *(const float4 *)&Ws[c0];
        float4 w2 = *(const float4 *)&Ws[128 + c0];
        float4 w3 = *(const float4 *)&Ws[256 + c0];
        float4 x1v = *(const float4 *)&g_x1[(size_t)gw * 128 + c0];
        float4 x2v = *(const float4 *)&g_x2[(size_t)gw * 128 + c0];
        float s = x1v.x * w1.x + x1v.y * w1.y + x1v.z * w1.z + x1v.w * w1.w
                + x2v.x * w2.x + x2v.y * w2.y + x2v.z * w2.z + x2v.w * w2.w
                + o.x * w3.x + o.y * w3.y + o.z * w3.z + o.w * w3.w;
        for (int off = 16; off; off >>= 1) s += __shfl_down_sync(0xFFFFFFFFu, s, off);
        if (lane == 0) g_ysc[gw] = sc * s;
    }
}

// ------------------------- score aggregate (scalar GCN) -------------------------
__global__ __launch_bounds__(256) void k_score_agg(const float *__restrict__ bs) {
    int gw = (blockIdx.x * 256 + threadIdx.x) >> 5;
    int lane = threadIdx.x & 31;
    if (gw >= NN) return;
    int start = g_rowptr[gw], end = g_rowptr[gw + 1];
    float s = 0.f;
    for (int e = start + lane; e < end; e += 32) s += g_ysc[g_csr[e]];
    for (int o = 16; o; o >>= 1) s += __shfl_down_sync(0xFFFFFFFFu, s, o);
    if (lane == 0) {
        float tot = s + g_ysc[gw];
        float sc = fmaf(rsqrtf((float)(g_degcnt[gw] + 1)), tot, bs[0]);
        g_score[gw] = sc;
        g_ukey[gw] = fkey(sc);
    }
}

// ------------------------- persistent-grid radix select + ties (1 kernel) ----------
__global__ __launch_bounds__(256) void k_radix() {
    __shared__ unsigned sh[256];
    __shared__ unsigned s_pref, s_kp;
    __shared__ unsigned s_phase;
    int t = threadIdx.x;
    int i = blockIdx.x * 256 + t;
    if (t == 0) s_phase = 0u;
    __syncthreads();

    unsigned prefix = 0u, kprime = (unsigned)KKEEP;
    unsigned mykey = (i < NN) ? g_ukey[i] : 0u;

#pragma unroll
    for (int pass = 0; pass < 4; ++pass) {
        sh[t] = 0u;
        __syncthreads();
        if (i < NN) {
            bool m = (pass == 0) || ((mykey >> (32 - 8 * pass)) == prefix);
            if (m) atomicAdd(&sh[(mykey >> (24 - 8 * pass)) & 255u], 1u);
        }
        __syncthreads();
        if (sh[t]) atomicAdd(&g_hist4[pass * 256 + t], sh[t]);
        __threadfence();
        __syncthreads();
        if (t == 0) {
            unsigned target = s_phase + (unsigned)gridDim.x;
            atomicAdd(&g_barcnt, 1u);
            while (atomicAdd(&g_barcnt, 0u) < target) {}
            s_phase = target;
        }
        __syncthreads();
        if (t == 0) {
            unsigned kp = kprime, c = 0;
            int b;
            for (b = 255; b >= 0; --b) {
                unsigned h = g_hist4[pass * 256 + b];
                if (c + h >= kp) break;
                c += h;
            }
            if (b < 0) b = 0;
            s_pref = (prefix << 8) | (unsigned)b;
            s_kp = kp - c;
        }
        __syncthreads();
        prefix = s_pref;
        kprime = s_kp;
    }

    if (i < NN) {
        g_gate[i] = tanhf(g_score[i]);
        if (mykey == prefix) {
            int p = atomicAdd(&g_nties, 1);
            g_tieidx[p] = i;
        }
    }
    if (blockIdx.x == 0 && t == 0) g_prefix = prefix;
    __threadfence();
    __syncthreads();
    if (t == 0) {
        unsigned target = s_phase + (unsigned)gridDim.x;
        atomicAdd(&g_barcnt, 1u);
        while (atomicAdd(&g_barcnt, 0u) < target) {}
        s_phase = target;
    }
    __syncthreads();
    if (blockIdx.x == 0) {
        int M = g_nties;
        unsigned R = kprime;
        for (int j = t; j < M; j += 256) {
            int idx = g_tieidx[j];
            unsigned rank = 0;
            for (int l = 0; l < M; ++l) rank += (g_tieidx[l] < idx) ? 1u : 0u;
            if (rank < R) g_tieflag[idx] = 1;
        }
    }
}

// ------------------------- pooling (max + sum over kept nodes, 384 dims) -------------------------
__global__ __launch_bounds__(384) void k_pool() {
    int c = threadIdx.x;
    const float *xa = (c < 128) ? g_x1 : ((c < 256) ? g_x2 : g_x3);
    int cc = c & 127;
    unsigned T = g_prefix;
    float mx = -3.402823466e38f, sm = 0.f;
    for (int i = blockIdx.x; i < NN; i += gridDim.x) {
        unsigned u = g_ukey[i];
        if (u < T) continue;
        if (u == T && !g_tieflag[i]) continue;
        float g = g_gate[i];
        float v = xa[(size_t)i * 128 + cc] * g;
        mx = fmaxf(mx, v);
        sm += v;
    }
    atomicMaxF(&g_gmax[c], mx);
    atomicAdd(&g_gsum[c], sm);
}

// ------------------------- final MLP head (single block) -------------------------
__global__ __launch_bounds__(128) void k_mlp(const float *__restrict__ Wl1, const float *__restrict__ bl1,
                                             const float *__restrict__ Wl2, const float *__restrict__ bl2,
                                             const float *__restrict__ Wl3, const float *__restrict__ bl3,
                                             float *__restrict__ out) {
    __shared__ float h[768], h1[128], h2[64], lg[10];
    int t = threadIdx.x;
    for (int c = t; c < 384; c += 128) {
        h[c] = g_gmax[c];
        h[384 + c] = g_gsum[c] * (1.0f / KKEEP);
    }
    __syncthreads();
    float s = bl1[t];
    for (int i = 0; i < 768; ++i) s = fmaf(h[i], Wl1[i * 128 + t], s);
    h1[t] = fmaxf(s, 0.f);
    __syncthreads();
    if (t < 64) {
        float s2 = bl2[t];
        for (int i = 0; i < 128; ++i) s2 = fmaf(h1[i], Wl2[i * 64 + t], s2);
        h2[t] = fmaxf(s2, 0.f);
    }
    __syncthreads();
    if (t < 10) {
        float s3 = bl3[t];
        for (int i = 0; i < 64; ++i) s3 = fmaf(h2[i], Wl3[i * 10 + t], s3);
        lg[t] = s3;
    }
    __syncthreads();
    if (t == 0) {
        float m = lg[0];
        for (int j = 1; j < 10; ++j) m = fmaxf(m, lg[j]);
        float se = 0.f;
        for (int j = 0; j < 10; ++j) se += expf(lg[j] - m);
        float lse = m + logf(se);
        for (int j = 0; j < 10; ++j) out[j] = lg[j] - lse;
    }
}

// ------------------------- launch -------------------------
extern "C" void kernel_launch(void *const *d_in, const int *in_sizes, int n_in,
                              void *d_out, int out_size) {
    const float *x      = (const float *)d_in[0];
    const int   *ei     = (const int *)d_in[1];   // int32
    const float *W1 = (const float *)d_in[3],  *b1  = (const float *)d_in[4];
    const float *W2 = (const float *)d_in[5],  *b2  = (const float *)d_in[6];
    const float *W3 = (const float *)d_in[7],  *b3  = (const float *)d_in[8];
    const float *Ws = (const float *)d_in[9],  *bs  = (const float *)d_in[10];
    const float *Wl1 = (const float *)d_in[11], *bl1 = (const float *)d_in[12];
    const float *Wl2 = (const float *)d_in[13], *bl2 = (const float *)d_in[14];
    const float *Wl3 = (const float *)d_in[15], *bl3 = (const float *)d_in[16];
    float *out = (float *)d_out;

    const int nblkN = (NN + 255) / 256;
    const int nblkE4 = (EE / 4 + 255) / 256;
    const int nblkW = (NN * 32 + 255) / 256;
    const int nblkT = (NN + 127) / 128;
    const int nblkS = (NN * 16 + 255) / 256;

    static cudaStream_t sCsr = nullptr, sPrep = nullptr;
    static cudaEvent_t evFork = nullptr, evCsr = nullptr, evPrep = nullptr;
    static bool inited = false;
    if (!inited) {
        cudaStreamCreateWithFlags(&sCsr, cudaStreamNonBlocking);
        cudaStreamCreateWithFlags(&sPrep, cudaStreamNonBlocking);
        cudaEventCreateWithFlags(&evFork, cudaEventDisableTiming);
        cudaEventCreateWithFlags(&evCsr, cudaEventDisableTiming);
        cudaEventCreateWithFlags(&evPrep, cudaEventDisableTiming);
        cudaFuncSetAttribute(k_gemm_mma, cudaFuncAttributeMaxDynamicSharedMemorySize, GT_SMEM_BYTES);
        inited = true;
    }

    // ---- origin: init + prepB1 only (GEMM-1 has no degcnt dep) ----
    k_init<<<nblkN, 256>>>();
    cudaEventRecord(evFork, 0);
    k_prepB<<<(FIN * 64 + 255) / 256, 256>>>(W1, FIN, 0);

    // ---- side stream 1: full edge pipeline (count + CSR), overlaps GEMM-1 ----
    cudaStreamWaitEvent(sCsr, evFork, 0);
    k_count<<<nblkE4, 256, 0, sCsr>>>(ei);
    k_chunksum<<<NCH, 256, 0, sCsr>>>();
    k_scanchunks<<<1, 1, 0, sCsr>>>();
    k_scanwrite<<<NCH, 1024, 0, sCsr>>>();
    k_scatter<<<nblkE4, 256, 0, sCsr>>>(ei);
    cudaEventRecord(evCsr, sCsr);

    // ---- side stream 2: prepB layers 1,2 ----
    cudaStreamWaitEvent(sPrep, evFork, 0);
    k_prepB<<<(HH * 64 + 255) / 256, 256, 0, sPrep>>>(W2, HH, 1);
    k_prepB<<<(HH * 64 + 255) / 256, 256, 0, sPrep>>>(W3, HH, 2);
    cudaEventRecord(evPrep, sPrep);

    // ---- origin: GCN layer 1 GEMM (unscaled; concurrent with edge pipeline) ----
    k_gemm_mma<<<nblkT, 256, GT_SMEM_BYTES>>>(x, 1, 0, FIN, 0, 0);
    cudaStreamWaitEvent(0, evCsr, 0);
    k_scale<<<nblkS, 256>>>();              // apply ds after count completes
    k_agg<<<nblkW, 256>>>(b1, 1, 0, nullptr);
    // layer 2 (epilogue-scaled)
    cudaStreamWaitEvent(0, evPrep, 0);
    k_gemm_mma<<<nblkT, 256, GT_SMEM_BYTES>>>(nullptr, 0, 1, HH, 1, 1);
    k_agg<<<nblkW, 256>>>(b2, 2, 0, nullptr);
    // layer 3 (+fused score linear)
    k_gemm_mma<<<nblkT, 256, GT_SMEM_BYTES>>>(nullptr, 0, 2, HH, 2, 1);
    k_agg<<<nblkW, 256>>>(b3, 3, 1, Ws);
    // score aggregate
    k_score_agg<<<nblkW, 256>>>(bs);
    // persistent-grid radix select + gate + ties
    k_radix<<<RBLK, 256>>>();
    // gated max/mean readout over kept nodes
    k_pool<<<512, 384>>>();
    // MLP head + log_softmax
    k_mlp<<<1, 128>>>(Wl1, bl1, Wl2, bl2, Wl3, bl3, out);
}